// round 2
// baseline (speedup 1.0000x reference)
#include <cuda_runtime.h>
#include <cstdint>

// Problem constants
#define HID   2048
#define NH    32
#define NKV   8
#define HD    64
#define FF    5632
#define BB    2
#define SS    2048
#define TOK   (BB*SS)           // 4096

// ---------------- scratch (alloc-free: __device__ globals) ----------------
__device__ float g_xnorm[TOK * HID];        // 32MB
__device__ float g_q   [TOK * NH * HD];     // 32MB
__device__ float g_k   [TOK * NKV * HD];    // 8MB
__device__ float g_v   [TOK * NKV * HD];    // 8MB
__device__ float g_attn[TOK * NH * HD];     // 32MB
__device__ float g_hid [TOK * HID];         // 32MB
__device__ float g_yn  [TOK * HID];         // 32MB
__device__ float g_gate[TOK * FF];          // 92MB
__device__ float g_up  [TOK * FF];          // 92MB

// ---------------- RMSNorm: one block per row of 2048 ----------------
__global__ __launch_bounds__(256) void rmsnorm_kernel(
    const float* __restrict__ x, const float* __restrict__ w, float* __restrict__ out)
{
    const int row = blockIdx.x;
    const float* xr = x + (size_t)row * HID;
    float ss = 0.f;
    // 2048 floats = 512 float4
    for (int i = threadIdx.x; i < 512; i += 256) {
        float4 v = ((const float4*)xr)[i];
        ss += v.x*v.x + v.y*v.y + v.z*v.z + v.w*v.w;
    }
    // reduce within warp
    #pragma unroll
    for (int o = 16; o > 0; o >>= 1) ss += __shfl_xor_sync(0xffffffffu, ss, o);
    __shared__ float red[8];
    if ((threadIdx.x & 31) == 0) red[threadIdx.x >> 5] = ss;
    __syncthreads();
    float tot = red[0];
    #pragma unroll
    for (int i = 1; i < 8; i++) tot += red[i];
    const float rs = rsqrtf(tot / (float)HID + 1e-6f);
    float* orow = out + (size_t)row * HID;
    for (int i = threadIdx.x; i < 512; i += 256) {
        float4 v = ((const float4*)xr)[i];
        float4 ww = ((const float4*)w)[i];
        float4 o;
        o.x = v.x * rs * ww.x; o.y = v.y * rs * ww.y;
        o.z = v.z * rs * ww.z; o.w = v.w * rs * ww.w;
        ((float4*)orow)[i] = o;
    }
}

// ---------------- Generic SGEMM: C[M,N] = A[M,K] @ B[K,N] (+ RES) ----------------
// BM=BN=128, BK=8, 256 threads, 8x8 microtile. All dims divide tiles exactly.
__global__ __launch_bounds__(256) void sgemm_kernel(
    int M, int N, int K,
    const float* __restrict__ A, const float* __restrict__ B,
    const float* __restrict__ RES, float* __restrict__ C)
{
    __shared__ float As[8][128];
    __shared__ float Bs[8][128];
    const int tid = threadIdx.x;
    const int brow = blockIdx.y, bcol = blockIdx.x;
    const float* Ab = A + (size_t)brow * 128 * K;
    const float* Bb = B + (size_t)bcol * 128;

    const int tr = tid >> 4;            // 0..15
    const int tc = tid & 15;            // 0..15
    const int arow = tid >> 1;          // 0..127
    const int acol = (tid & 1) * 4;     // 0 or 4
    const int brB  = tid >> 5;          // 0..7
    const int bcB  = (tid & 31) * 4;    // 0..124

    float acc[8][8];
    #pragma unroll
    for (int i = 0; i < 8; i++)
        #pragma unroll
        for (int j = 0; j < 8; j++) acc[i][j] = 0.f;

    for (int k0 = 0; k0 < K; k0 += 8) {
        float4 av = *(const float4*)(Ab + (size_t)arow * K + k0 + acol);
        As[acol + 0][arow] = av.x;
        As[acol + 1][arow] = av.y;
        As[acol + 2][arow] = av.z;
        As[acol + 3][arow] = av.w;
        *(float4*)&Bs[brB][bcB] = *(const float4*)(Bb + (size_t)(k0 + brB) * N + bcB);
        __syncthreads();

        #pragma unroll
        for (int kk = 0; kk < 8; kk++) {
            float ra[8], rb[8];
            *(float4*)&ra[0] = *(const float4*)&As[kk][tr * 8];
            *(float4*)&ra[4] = *(const float4*)&As[kk][tr * 8 + 4];
            *(float4*)&rb[0] = *(const float4*)&Bs[kk][tc * 8];
            *(float4*)&rb[4] = *(const float4*)&Bs[kk][tc * 8 + 4];
            #pragma unroll
            for (int i = 0; i < 8; i++)
                #pragma unroll
                for (int j = 0; j < 8; j++)
                    acc[i][j] += ra[i] * rb[j];
        }
        __syncthreads();
    }

    #pragma unroll
    for (int i = 0; i < 8; i++) {
        const size_t row = (size_t)brow * 128 + tr * 8 + i;
        #pragma unroll
        for (int j4 = 0; j4 < 2; j4++) {
            const size_t col = (size_t)bcol * 128 + tc * 8 + j4 * 4;
            float4 o;
            o.x = acc[i][j4*4+0]; o.y = acc[i][j4*4+1];
            o.z = acc[i][j4*4+2]; o.w = acc[i][j4*4+3];
            if (RES) {
                float4 rr = *(const float4*)(RES + row * N + col);
                o.x += rr.x; o.y += rr.y; o.z += rr.z; o.w += rr.w;
            }
            *(float4*)(C + row * N + col) = o;
        }
    }
}

// ---------------- RoPE (in-place on q and k) ----------------
__global__ void rope_kernel(float* __restrict__ q, float* __restrict__ k)
{
    const int NQ = TOK * NH * (HD / 2);      // 4,194,304
    const int NK = TOK * NKV * (HD / 2);     // 1,048,576
    int idx = blockIdx.x * blockDim.x + threadIdx.x;
    float* p;
    int token, i;
    if (idx < NQ) {
        token = idx >> 10;                    // / (NH*32)
        const int rem = idx & 1023;
        const int head = rem >> 5;
        i = rem & 31;
        p = q + (size_t)token * (NH * HD) + head * HD;
    } else {
        idx -= NQ;
        if (idx >= NK) return;
        token = idx >> 8;                     // / (NKV*32)
        const int rem = idx & 255;
        const int head = rem >> 5;
        i = rem & 31;
        p = k + (size_t)token * (NKV * HD) + head * HD;
    }
    const int pos = token & (SS - 1);
    const float inv_freq = powf(10000.0f, -(float)i / 32.0f);
    const float ang = (float)pos * inv_freq;
    const float c = cosf(ang), s = sinf(ang);
    const float x1 = p[i], x2 = p[i + 32];
    p[i]      = x1 * c - x2 * s;
    p[i + 32] = x2 * c + x1 * s;
}

// ---------------- Flash attention (causal, GQA rep=4, fp32) ----------------
// grid: (S/64, NH, B); 256 threads. Thread t: q-row r=t>>2, dim-quarter tg=t&3.
__global__ __launch_bounds__(256) void flash_attn_kernel(
    const float* __restrict__ Q, const float* __restrict__ Kg,
    const float* __restrict__ Vg, float* __restrict__ O)
{
    __shared__ float Ks[64][68];
    __shared__ float Vs[64][68];
    const int b = blockIdx.z, h = blockIdx.y, qt = blockIdx.x;
    const int kvh = h >> 2;
    const int tid = threadIdx.x;
    const int r = tid >> 2;
    const int tg = tid & 3;
    const int q0 = qt * 64;
    const size_t tokbase = (size_t)b * SS;

    float4 qv[4];
    {
        const float* qp = Q + (tokbase + q0 + r) * (NH * HD) + h * HD + tg * 16;
        qv[0] = *(const float4*)(qp + 0);
        qv[1] = *(const float4*)(qp + 4);
        qv[2] = *(const float4*)(qp + 8);
        qv[3] = *(const float4*)(qp + 12);
    }
    float acc[16];
    #pragma unroll
    for (int i = 0; i < 16; i++) acc[i] = 0.f;
    float m = -1e30f, l = 0.f;
    const int qglob = q0 + r;

    for (int kt = 0; kt <= qt; kt++) {
        __syncthreads();   // protect prev-iter smem reads
        for (int i = tid; i < 64 * 16; i += 256) {
            const int row = i >> 4, c4 = (i & 15) * 4;
            const size_t g = (tokbase + kt * 64 + row) * (NKV * HD) + kvh * HD + c4;
            *(float4*)&Ks[row][c4] = *(const float4*)(Kg + g);
            *(float4*)&Vs[row][c4] = *(const float4*)(Vg + g);
        }
        __syncthreads();

        float sc[64];
        #pragma unroll 8
        for (int j = 0; j < 64; j++) {
            float4 k0 = *(const float4*)&Ks[j][tg * 16 + 0];
            float4 k1 = *(const float4*)&Ks[j][tg * 16 + 4];
            float4 k2 = *(const float4*)&Ks[j][tg * 16 + 8];
            float4 k3 = *(const float4*)&Ks[j][tg * 16 + 12];
            float s = qv[0].x*k0.x + qv[0].y*k0.y + qv[0].z*k0.z + qv[0].w*k0.w;
            s += qv[1].x*k1.x + qv[1].y*k1.y + qv[1].z*k1.z + qv[1].w*k1.w;
            s += qv[2].x*k2.x + qv[2].y*k2.y + qv[2].z*k2.z + qv[2].w*k2.w;
            s += qv[3].x*k3.x + qv[3].y*k3.y + qv[3].z*k3.z + qv[3].w*k3.w;
            sc[j] = s;
        }
        #pragma unroll
        for (int j = 0; j < 64; j++) {
            sc[j] += __shfl_xor_sync(0xffffffffu, sc[j], 1);
            sc[j] += __shfl_xor_sync(0xffffffffu, sc[j], 2);
        }
        const int kbase = kt * 64;
        float mt = -1e30f;
        #pragma unroll
        for (int j = 0; j < 64; j++) {
            sc[j] = (kbase + j <= qglob) ? sc[j] * 0.125f : -1e30f;
            mt = fmaxf(mt, sc[j]);
        }
        const float mnew = fmaxf(m, mt);
        const float scale = __expf(m - mnew);
        float psum = 0.f;
        #pragma unroll
        for (int j = 0; j < 64; j++) { sc[j] = __expf(sc[j] - mnew); psum += sc[j]; }
        l = l * scale + psum;
        m = mnew;
        #pragma unroll
        for (int i = 0; i < 16; i++) acc[i] *= scale;
        #pragma unroll 8
        for (int j = 0; j < 64; j++) {
            const float p = sc[j];
            #pragma unroll
            for (int u = 0; u < 4; u++) {
                float4 vv = *(const float4*)&Vs[j][tg * 16 + u * 4];
                acc[u*4+0] += p * vv.x;
                acc[u*4+1] += p * vv.y;
                acc[u*4+2] += p * vv.z;
                acc[u*4+3] += p * vv.w;
            }
        }
    }
    const float inv = 1.f / l;
    float* op = O + (tokbase + q0 + r) * (NH * HD) + h * HD + tg * 16;
    #pragma unroll
    for (int u = 0; u < 4; u++) {
        float4 o;
        o.x = acc[u*4+0] * inv; o.y = acc[u*4+1] * inv;
        o.z = acc[u*4+2] * inv; o.w = acc[u*4+3] * inv;
        *(float4*)(op + u * 4) = o;
    }
}

// ---------------- SwiGLU: gate <- silu(gate) * up ----------------
__global__ void swiglu_kernel(float* __restrict__ gate, const float* __restrict__ up)
{
    const int idx = blockIdx.x * blockDim.x + threadIdx.x;  // float4 index
    const int n4 = (TOK * FF) / 4;
    if (idx >= n4) return;
    float4 g = ((const float4*)gate)[idx];
    float4 u = ((const float4*)up)[idx];
    g.x = g.x / (1.f + __expf(-g.x)) * u.x;
    g.y = g.y / (1.f + __expf(-g.y)) * u.y;
    g.z = g.z / (1.f + __expf(-g.z)) * u.z;
    g.w = g.w / (1.f + __expf(-g.w)) * u.w;
    ((float4*)gate)[idx] = g;
}

// ---------------- launch ----------------
extern "C" void kernel_launch(void* const* d_in, const int* in_sizes, int n_in,
                              void* d_out, int out_size)
{
    const float* hs     = (const float*)d_in[0];
    const float* wq     = (const float*)d_in[1];
    const float* wk     = (const float*)d_in[2];
    const float* wv     = (const float*)d_in[3];
    const float* wo     = (const float*)d_in[4];
    const float* w_gate = (const float*)d_in[5];
    const float* w_up   = (const float*)d_in[6];
    const float* w_down = (const float*)d_in[7];
    const float* norm1  = (const float*)d_in[8];
    const float* norm2  = (const float*)d_in[9];
    float* out = (float*)d_out;

    float *xn, *q, *k, *v, *attn, *hid, *yn, *gate, *up;
    cudaGetSymbolAddress((void**)&xn,   g_xnorm);
    cudaGetSymbolAddress((void**)&q,    g_q);
    cudaGetSymbolAddress((void**)&k,    g_k);
    cudaGetSymbolAddress((void**)&v,    g_v);
    cudaGetSymbolAddress((void**)&attn, g_attn);
    cudaGetSymbolAddress((void**)&hid,  g_hid);
    cudaGetSymbolAddress((void**)&yn,   g_yn);
    cudaGetSymbolAddress((void**)&gate, g_gate);
    cudaGetSymbolAddress((void**)&up,   g_up);

    // 1) pre-norm
    rmsnorm_kernel<<<TOK, 256>>>(hs, norm1, xn);
    // 2) QKV projections
    sgemm_kernel<<<dim3(2048/128, TOK/128), 256>>>(TOK, 2048, HID, xn, wq, nullptr, q);
    sgemm_kernel<<<dim3( 512/128, TOK/128), 256>>>(TOK,  512, HID, xn, wk, nullptr, k);
    sgemm_kernel<<<dim3( 512/128, TOK/128), 256>>>(TOK,  512, HID, xn, wv, nullptr, v);
    // 3) RoPE on q,k
    {
        const int total = TOK * NH * (HD/2) + TOK * NKV * (HD/2);
        rope_kernel<<<(total + 255) / 256, 256>>>(q, k);
    }
    // 4) causal GQA flash attention
    flash_attn_kernel<<<dim3(SS/64, NH, BB), 256>>>(q, k, v, attn);
    // 5) output projection + residual
    sgemm_kernel<<<dim3(2048/128, TOK/128), 256>>>(TOK, 2048, NH*HD, attn, wo, hs, hid);
    // 6) post-norm
    rmsnorm_kernel<<<TOK, 256>>>(hid, norm2, yn);
    // 7) gate/up projections
    sgemm_kernel<<<dim3(FF/128, TOK/128), 256>>>(TOK, FF, HID, yn, w_gate, nullptr, gate);
    sgemm_kernel<<<dim3(FF/128, TOK/128), 256>>>(TOK, FF, HID, yn, w_up,   nullptr, up);
    // 8) SwiGLU
    swiglu_kernel<<<((TOK*FF/4) + 255) / 256, 256>>>(gate, up);
    // 9) down projection + residual -> output
    sgemm_kernel<<<dim3(HID/128, TOK/128), 256>>>(TOK, HID, FF, gate, w_down, hid, out);
}

// round 4
// speedup vs baseline: 1.9000x; 1.9000x over previous
#include <cuda_runtime.h>
#include <cstdint>

// Problem constants
#define HID   2048
#define NH    32
#define NKV   8
#define HD    64
#define FF    5632
#define BB    2
#define SS    2048
#define TOK   (BB*SS)           // 4096

// ---------------- scratch (alloc-free: __device__ globals) ----------------
__device__ float g_xnorm[TOK * HID];
__device__ float g_q   [TOK * NH * HD];
__device__ float g_k   [TOK * NKV * HD];
__device__ float g_v   [TOK * NKV * HD];
__device__ float g_attn[TOK * NH * HD];
__device__ float g_hid [TOK * HID];
__device__ float g_yn  [TOK * HID];
__device__ float g_gate[TOK * FF];
__device__ float g_up  [TOK * FF];
// transposed (N-major -> K-contiguous) + tf32-rounded weights
__device__ float g_wqT[2048 * 2048];
__device__ float g_wkT[ 512 * 2048];
__device__ float g_wvT[ 512 * 2048];
__device__ float g_woT[2048 * 2048];
__device__ float g_wgT[FF * 2048];
__device__ float g_wuT[FF * 2048];
__device__ float g_wdT[2048 * FF];

// ---------------- helpers ----------------
__device__ __forceinline__ uint32_t s2u(const void* p) {
    uint32_t a;
    asm("{ .reg .u64 t; cvta.to.shared.u64 t, %1; cvt.u32.u64 %0, t; }" : "=r"(a) : "l"(p));
    return a;
}
__device__ __forceinline__ float rna_tf32(float x) {
    float y;
    asm("cvt.rna.tf32.f32 %0, %1;" : "=f"(y) : "f"(x));
    return y;
}
__device__ __forceinline__ void cpa16(uint32_t s, const void* g) {
    asm volatile("cp.async.cg.shared.global [%0], [%1], 16;" :: "r"(s), "l"(g));
}
__device__ __forceinline__ void cp_commit() { asm volatile("cp.async.commit_group;" ::); }
template<int N> __device__ __forceinline__ void cp_wait() {
    asm volatile("cp.async.wait_group %0;" :: "n"(N));
}
__device__ __forceinline__ void mma8(float* c, const uint32_t* a, const uint32_t* b) {
    asm volatile(
        "mma.sync.aligned.m16n8k8.row.col.f32.tf32.tf32.f32 "
        "{%0,%1,%2,%3},{%4,%5,%6,%7},{%8,%9},{%0,%1,%2,%3};"
        : "+f"(c[0]), "+f"(c[1]), "+f"(c[2]), "+f"(c[3])
        : "r"(a[0]), "r"(a[1]), "r"(a[2]), "r"(a[3]), "r"(b[0]), "r"(b[1]));
}

// ---------------- tf32 mma.sync GEMM: C[M,N] = A[M,K] @ BT[N,K]^T (+RES) ----------------
// BM=128, BN=256, BK=32 floats, 3-stage cp.async, 8 warps x (64x64 warp tile).
// Smem row stride 36 floats (144B): conflict-free fragment loads ((4g+t)%32 covers all banks).
#define BM      128
#define BN      256
#define BKF     32
#define NSTAGE  3
#define ASTRIDE 36
#define ATILEF  (BM * ASTRIDE)            // 4608 floats
#define BTILEF  (BN * ASTRIDE)            // 9216 floats
#define STAGEF  (ATILEF + BTILEF)         // 13824 floats = 55296 B
#define GEMM_SMEM (NSTAGE * STAGEF * 4)   // 165888 B

__global__ __launch_bounds__(256, 1) void gemm_mma(
    int M, int N, int K,
    const float* __restrict__ A, const float* __restrict__ BT,
    const float* __restrict__ RES, float* __restrict__ C)
{
    extern __shared__ float sm[];
    const int tid = threadIdx.x;
    const int wid = tid >> 5, lane = tid & 31;
    const int g = lane >> 2, t = lane & 3;
    const int bm0 = blockIdx.y * BM, bn0 = blockIdx.x * BN;
    const int wm0 = (wid & 1) * 64;       // warp row offset in tile
    const int wn0 = (wid >> 1) * 64;      // warp col offset in tile

    float acc[4][8][4];
    #pragma unroll
    for (int mi = 0; mi < 4; mi++)
        #pragma unroll
        for (int ni = 0; ni < 8; ni++)
            #pragma unroll
            for (int u = 0; u < 4; u++) acc[mi][ni][u] = 0.f;

    const int NC = K / BKF;

    auto issue = [&](int j) {
        float* st = sm + (j % NSTAGE) * STAGEF;
        const int k0 = j * BKF;
        #pragma unroll
        for (int i = 0; i < 4; i++) {               // A: 1024 float4
            const int idx = tid + i * 256;
            const int r = idx >> 3, f = idx & 7;
            cpa16(s2u(st + r * ASTRIDE + f * 4), A + (size_t)(bm0 + r) * K + k0 + f * 4);
        }
        float* stb = st + ATILEF;
        #pragma unroll
        for (int i = 0; i < 8; i++) {               // B: 2048 float4
            const int idx = tid + i * 256;
            const int r = idx >> 3, f = idx & 7;
            cpa16(s2u(stb + r * ASTRIDE + f * 4), BT + (size_t)(bn0 + r) * K + k0 + f * 4);
        }
        cp_commit();
    };

    for (int j = 0; j < NSTAGE; j++) issue(j);      // NC >= NSTAGE for all our shapes

    for (int c = 0; c < NC; c++) {
        // wait until chunk c is resident (account for drained issue queue at tail)
        const int inflight_after = (c + NSTAGE <= NC ? c + NSTAGE : NC) - (c + 1);
        if (inflight_after >= 2)      cp_wait<2>();
        else if (inflight_after == 1) cp_wait<1>();
        else                          cp_wait<0>();
        __syncthreads();

        const float* sa = sm + (c % NSTAGE) * STAGEF;
        const float* sb = sa + ATILEF;
        #pragma unroll
        for (int kk = 0; kk < 4; kk++) {
            const int k0 = kk * 8;
            uint32_t af[4][4];
            #pragma unroll
            for (int mi = 0; mi < 4; mi++) {
                const float* p = sa + (wm0 + mi * 16 + g) * ASTRIDE + k0 + t;
                af[mi][0] = __float_as_uint(p[0]);
                af[mi][1] = __float_as_uint(p[8 * ASTRIDE]);
                af[mi][2] = __float_as_uint(p[4]);
                af[mi][3] = __float_as_uint(p[8 * ASTRIDE + 4]);
            }
            uint32_t bf[8][2];
            #pragma unroll
            for (int ni = 0; ni < 8; ni++) {
                const float* p = sb + (wn0 + ni * 8 + g) * ASTRIDE + k0 + t;
                bf[ni][0] = __float_as_uint(p[0]);
                bf[ni][1] = __float_as_uint(p[4]);
            }
            #pragma unroll
            for (int mi = 0; mi < 4; mi++)
                #pragma unroll
                for (int ni = 0; ni < 8; ni++)
                    mma8(acc[mi][ni], af[mi], bf[ni]);
        }
        __syncthreads();
        if (c + NSTAGE < NC) issue(c + NSTAGE);
    }

    // epilogue: fragment layout -> C rows (g, g+8), cols (2t, 2t+1)
    #pragma unroll
    for (int mi = 0; mi < 4; mi++) {
        const int row0 = bm0 + wm0 + mi * 16 + g;
        #pragma unroll
        for (int ni = 0; ni < 8; ni++) {
            const int col = bn0 + wn0 + ni * 8 + 2 * t;
            float2 d0 = make_float2(acc[mi][ni][0], acc[mi][ni][1]);
            float2 d1 = make_float2(acc[mi][ni][2], acc[mi][ni][3]);
            if (RES) {
                float2 r0 = *(const float2*)(RES + (size_t)row0 * N + col);
                float2 r1 = *(const float2*)(RES + (size_t)(row0 + 8) * N + col);
                d0.x += r0.x; d0.y += r0.y;
                d1.x += r1.x; d1.y += r1.y;
            }
            *(float2*)(C + (size_t)row0 * N + col)       = d0;
            *(float2*)(C + (size_t)(row0 + 8) * N + col) = d1;
        }
    }
}

// ---------------- transpose + tf32 round: out[C,R] = rna(in[R,C]^T) ----------------
__global__ __launch_bounds__(256) void transpose_rna_kernel(
    const float* __restrict__ in, float* __restrict__ out, int R, int C)
{
    __shared__ float t[32][33];
    const int bx = blockIdx.x * 32;
    const int by = blockIdx.y * 32;
    const int x = threadIdx.x, y = threadIdx.y;  // (32, 8)
    #pragma unroll
    for (int j = 0; j < 32; j += 8)
        t[y + j][x] = in[(size_t)(by + y + j) * C + bx + x];
    __syncthreads();
    #pragma unroll
    for (int j = 0; j < 32; j += 8)
        out[(size_t)(bx + y + j) * R + by + x] = rna_tf32(t[x][y + j]);
}

// ---------------- RMSNorm (tf32-rounded output) ----------------
__global__ __launch_bounds__(256) void rmsnorm_kernel(
    const float* __restrict__ x, const float* __restrict__ w, float* __restrict__ out)
{
    const int row = blockIdx.x;
    const float* xr = x + (size_t)row * HID;
    float ss = 0.f;
    for (int i = threadIdx.x; i < 512; i += 256) {
        float4 v = ((const float4*)xr)[i];
        ss += v.x*v.x + v.y*v.y + v.z*v.z + v.w*v.w;
    }
    #pragma unroll
    for (int o = 16; o > 0; o >>= 1) ss += __shfl_xor_sync(0xffffffffu, ss, o);
    __shared__ float red[8];
    if ((threadIdx.x & 31) == 0) red[threadIdx.x >> 5] = ss;
    __syncthreads();
    float tot = red[0];
    #pragma unroll
    for (int i = 1; i < 8; i++) tot += red[i];
    const float rs = rsqrtf(tot / (float)HID + 1e-6f);
    float* orow = out + (size_t)row * HID;
    for (int i = threadIdx.x; i < 512; i += 256) {
        float4 v = ((const float4*)xr)[i];
        float4 ww = ((const float4*)w)[i];
        float4 o;
        o.x = rna_tf32(v.x * rs * ww.x); o.y = rna_tf32(v.y * rs * ww.y);
        o.z = rna_tf32(v.z * rs * ww.z); o.w = rna_tf32(v.w * rs * ww.w);
        ((float4*)orow)[i] = o;
    }
}

// ---------------- RoPE (in-place on q and k; tf32-rounded for next GEMM) ----------------
__global__ void rope_kernel(float* __restrict__ q, float* __restrict__ k)
{
    const int NQ = TOK * NH * (HD / 2);
    const int NK = TOK * NKV * (HD / 2);
    int idx = blockIdx.x * blockDim.x + threadIdx.x;
    float* p;
    int token, i;
    if (idx < NQ) {
        token = idx >> 10;
        const int rem = idx & 1023;
        const int head = rem >> 5;
        i = rem & 31;
        p = q + (size_t)token * (NH * HD) + head * HD;
    } else {
        idx -= NQ;
        if (idx >= NK) return;
        token = idx >> 8;
        const int rem = idx & 255;
        const int head = rem >> 5;
        i = rem & 31;
        p = k + (size_t)token * (NKV * HD) + head * HD;
    }
    const int pos = token & (SS - 1);
    const float inv_freq = powf(10000.0f, -(float)i / 32.0f);
    const float ang = (float)pos * inv_freq;
    const float c = cosf(ang), s = sinf(ang);
    const float x1 = p[i], x2 = p[i + 32];
    p[i]      = x1 * c - x2 * s;
    p[i + 32] = x2 * c + x1 * s;
}

// ---------------- Flash attention (causal, GQA rep=4, fp32; tf32-rounded out) ----------------
__global__ __launch_bounds__(256) void flash_attn_kernel(
    const float* __restrict__ Q, const float* __restrict__ Kg,
    const float* __restrict__ Vg, float* __restrict__ O)
{
    __shared__ float Ks[64][68];
    __shared__ float Vs[64][68];
    const int b = blockIdx.z, h = blockIdx.y, qt = blockIdx.x;
    const int kvh = h >> 2;
    const int tid = threadIdx.x;
    const int r = tid >> 2;
    const int tg = tid & 3;
    const int q0 = qt * 64;
    const size_t tokbase = (size_t)b * SS;

    float4 qv[4];
    {
        const float* qp = Q + (tokbase + q0 + r) * (NH * HD) + h * HD + tg * 16;
        qv[0] = *(const float4*)(qp + 0);
        qv[1] = *(const float4*)(qp + 4);
        qv[2] = *(const float4*)(qp + 8);
        qv[3] = *(const float4*)(qp + 12);
    }
    float acc[16];
    #pragma unroll
    for (int i = 0; i < 16; i++) acc[i] = 0.f;
    float m = -1e30f, l = 0.f;
    const int qglob = q0 + r;

    for (int kt = 0; kt <= qt; kt++) {
        __syncthreads();
        for (int i = tid; i < 64 * 16; i += 256) {
            const int row = i >> 4, c4 = (i & 15) * 4;
            const size_t g = (tokbase + kt * 64 + row) * (NKV * HD) + kvh * HD + c4;
            *(float4*)&Ks[row][c4] = *(const float4*)(Kg + g);
            *(float4*)&Vs[row][c4] = *(const float4*)(Vg + g);
        }
        __syncthreads();

        float sc[64];
        #pragma unroll 8
        for (int j = 0; j < 64; j++) {
            float4 k0 = *(const float4*)&Ks[j][tg * 16 + 0];
            float4 k1 = *(const float4*)&Ks[j][tg * 16 + 4];
            float4 k2 = *(const float4*)&Ks[j][tg * 16 + 8];
            float4 k3 = *(const float4*)&Ks[j][tg * 16 + 12];
            float s = qv[0].x*k0.x + qv[0].y*k0.y + qv[0].z*k0.z + qv[0].w*k0.w;
            s += qv[1].x*k1.x + qv[1].y*k1.y + qv[1].z*k1.z + qv[1].w*k1.w;
            s += qv[2].x*k2.x + qv[2].y*k2.y + qv[2].z*k2.z + qv[2].w*k2.w;
            s += qv[3].x*k3.x + qv[3].y*k3.y + qv[3].z*k3.z + qv[3].w*k3.w;
            sc[j] = s;
        }
        #pragma unroll
        for (int j = 0; j < 64; j++) {
            sc[j] += __shfl_xor_sync(0xffffffffu, sc[j], 1);
            sc[j] += __shfl_xor_sync(0xffffffffu, sc[j], 2);
        }
        const int kbase = kt * 64;
        float mt = -1e30f;
        #pragma unroll
        for (int j = 0; j < 64; j++) {
            sc[j] = (kbase + j <= qglob) ? sc[j] * 0.125f : -1e30f;
            mt = fmaxf(mt, sc[j]);
        }
        const float mnew = fmaxf(m, mt);
        const float scale = __expf(m - mnew);
        float psum = 0.f;
        #pragma unroll
        for (int j = 0; j < 64; j++) { sc[j] = __expf(sc[j] - mnew); psum += sc[j]; }
        l = l * scale + psum;
        m = mnew;
        #pragma unroll
        for (int i = 0; i < 16; i++) acc[i] *= scale;
        #pragma unroll 8
        for (int j = 0; j < 64; j++) {
            const float p = sc[j];
            #pragma unroll
            for (int u = 0; u < 4; u++) {
                float4 vv = *(const float4*)&Vs[j][tg * 16 + u * 4];
                acc[u*4+0] += p * vv.x;
                acc[u*4+1] += p * vv.y;
                acc[u*4+2] += p * vv.z;
                acc[u*4+3] += p * vv.w;
            }
        }
    }
    const float inv = 1.f / l;
    float* op = O + (tokbase + q0 + r) * (NH * HD) + h * HD + tg * 16;
    #pragma unroll
    for (int u = 0; u < 4; u++) {
        float4 o;
        o.x = rna_tf32(acc[u*4+0] * inv); o.y = rna_tf32(acc[u*4+1] * inv);
        o.z = rna_tf32(acc[u*4+2] * inv); o.w = rna_tf32(acc[u*4+3] * inv);
        *(float4*)(op + u * 4) = o;
    }
}

// ---------------- SwiGLU: gate <- rna(silu(gate) * up) ----------------
__global__ void swiglu_kernel(float* __restrict__ gate, const float* __restrict__ up)
{
    const int idx = blockIdx.x * blockDim.x + threadIdx.x;
    const int n4 = (TOK * FF) / 4;
    if (idx >= n4) return;
    float4 g = ((const float4*)gate)[idx];
    float4 u = ((const float4*)up)[idx];
    g.x = rna_tf32(g.x / (1.f + __expf(-g.x)) * u.x);
    g.y = rna_tf32(g.y / (1.f + __expf(-g.y)) * u.y);
    g.z = rna_tf32(g.z / (1.f + __expf(-g.z)) * u.z);
    g.w = rna_tf32(g.w / (1.f + __expf(-g.w)) * u.w);
    ((float4*)gate)[idx] = g;
}

// ---------------- launch ----------------
extern "C" void kernel_launch(void* const* d_in, const int* in_sizes, int n_in,
                              void* d_out, int out_size)
{
    const float* hs     = (const float*)d_in[0];
    const float* wq     = (const float*)d_in[1];
    const float* wk     = (const float*)d_in[2];
    const float* wv     = (const float*)d_in[3];
    const float* wo     = (const float*)d_in[4];
    const float* w_gate = (const float*)d_in[5];
    const float* w_up   = (const float*)d_in[6];
    const float* w_down = (const float*)d_in[7];
    const float* norm1  = (const float*)d_in[8];
    const float* norm2  = (const float*)d_in[9];
    float* out = (float*)d_out;

    float *xn, *q, *k, *v, *attn, *hid, *yn, *gate, *up;
    float *wqT, *wkT, *wvT, *woT, *wgT, *wuT, *wdT;
    cudaGetSymbolAddress((void**)&xn,   g_xnorm);
    cudaGetSymbolAddress((void**)&q,    g_q);
    cudaGetSymbolAddress((void**)&k,    g_k);
    cudaGetSymbolAddress((void**)&v,    g_v);
    cudaGetSymbolAddress((void**)&attn, g_attn);
    cudaGetSymbolAddress((void**)&hid,  g_hid);
    cudaGetSymbolAddress((void**)&yn,   g_yn);
    cudaGetSymbolAddress((void**)&gate, g_gate);
    cudaGetSymbolAddress((void**)&up,   g_up);
    cudaGetSymbolAddress((void**)&wqT,  g_wqT);
    cudaGetSymbolAddress((void**)&wkT,  g_wkT);
    cudaGetSymbolAddress((void**)&wvT,  g_wvT);
    cudaGetSymbolAddress((void**)&woT,  g_woT);
    cudaGetSymbolAddress((void**)&wgT,  g_wgT);
    cudaGetSymbolAddress((void**)&wuT,  g_wuT);
    cudaGetSymbolAddress((void**)&wdT,  g_wdT);

    cudaFuncSetAttribute(gemm_mma, cudaFuncAttributeMaxDynamicSharedMemorySize, GEMM_SMEM);

    const dim3 tb(32, 8);
    // W^T (K-contiguous rows for mma B operand) + tf32 rounding
    transpose_rna_kernel<<<dim3(2048/32, 2048/32), tb>>>(wq,     wqT, 2048, 2048);
    transpose_rna_kernel<<<dim3( 512/32, 2048/32), tb>>>(wk,     wkT, 2048,  512);
    transpose_rna_kernel<<<dim3( 512/32, 2048/32), tb>>>(wv,     wvT, 2048,  512);
    transpose_rna_kernel<<<dim3(2048/32, 2048/32), tb>>>(wo,     woT, 2048, 2048);
    transpose_rna_kernel<<<dim3(  FF/32, 2048/32), tb>>>(w_gate, wgT, 2048,   FF);
    transpose_rna_kernel<<<dim3(  FF/32, 2048/32), tb>>>(w_up,   wuT, 2048,   FF);
    transpose_rna_kernel<<<dim3(2048/32,   FF/32), tb>>>(w_down, wdT,   FF, 2048);

    // 1) pre-norm (tf32-rounded)
    rmsnorm_kernel<<<TOK, 256>>>(hs, norm1, xn);
    // 2) QKV projections (tf32 mma.sync)
    gemm_mma<<<dim3(2048/BN, TOK/BM), 256, GEMM_SMEM>>>(TOK, 2048, HID, xn, wqT, nullptr, q);
    gemm_mma<<<dim3( 512/BN, TOK/BM), 256, GEMM_SMEM>>>(TOK,  512, HID, xn, wkT, nullptr, k);
    gemm_mma<<<dim3( 512/BN, TOK/BM), 256, GEMM_SMEM>>>(TOK,  512, HID, xn, wvT, nullptr, v);
    // 3) RoPE
    {
        const int total = TOK * NH * (HD/2) + TOK * NKV * (HD/2);
        rope_kernel<<<(total + 255) / 256, 256>>>(q, k);
    }
    // 4) causal GQA flash attention (fp32)
    flash_attn_kernel<<<dim3(SS/64, NH, BB), 256>>>(q, k, v, attn);
    // 5) output projection + residual
    gemm_mma<<<dim3(2048/BN, TOK/BM), 256, GEMM_SMEM>>>(TOK, 2048, NH*HD, attn, woT, hs, hid);
    // 6) post-norm (tf32-rounded)
    rmsnorm_kernel<<<TOK, 256>>>(hid, norm2, yn);
    // 7) gate/up projections
    gemm_mma<<<dim3(FF/BN, TOK/BM), 256, GEMM_SMEM>>>(TOK, FF, HID, yn, wgT, nullptr, gate);
    gemm_mma<<<dim3(FF/BN, TOK/BM), 256, GEMM_SMEM>>>(TOK, FF, HID, yn, wuT, nullptr, up);
    // 8) SwiGLU (tf32-rounded)
    swiglu_kernel<<<((TOK*FF/4) + 255) / 256, 256>>>(gate, up);
    // 9) down projection + residual -> output
    gemm_mma<<<dim3(HID/BN, TOK/BM), 256, GEMM_SMEM>>>(TOK, HID, FF, gate, wdT, hid, out);
}

// round 5
// speedup vs baseline: 8.7405x; 4.6001x over previous
#include <cuda_runtime.h>
#include <cuda_fp16.h>
#include <cstdint>

// Problem constants
#define HID   2048
#define NH    32
#define NKV   8
#define HD    64
#define FF    5632
#define BB    2
#define SS    2048
#define TOK   (BB*SS)           // 4096

// ---------------- scratch (alloc-free: __device__ globals) ----------------
__device__ float  g_q   [TOK * NH * HD];
__device__ float  g_k   [TOK * NKV * HD];
__device__ float  g_v   [TOK * NKV * HD];
__device__ float  g_hid [TOK * HID];
__device__ float  g_gate[TOK * FF];
__device__ float  g_up  [TOK * FF];
__device__ __half g_xnh [TOK * HID];
__device__ __half g_qh  [TOK * NH * HD];
__device__ __half g_kh  [TOK * NKV * HD];
__device__ __half g_vh  [TOK * NKV * HD];
__device__ __half g_attnh[TOK * NH * HD];
__device__ __half g_ynh [TOK * HID];
__device__ __half g_gateh[TOK * FF];
// transposed (N-major -> K-contiguous) fp16 weights
__device__ __half g_wqT[2048 * 2048];
__device__ __half g_wkT[ 512 * 2048];
__device__ __half g_wvT[ 512 * 2048];
__device__ __half g_woT[2048 * 2048];
__device__ __half g_wgT[FF * 2048];
__device__ __half g_wuT[FF * 2048];
__device__ __half g_wdT[2048 * FF];

// ---------------- helpers ----------------
__device__ __forceinline__ uint32_t s2u(const void* p) {
    uint32_t a;
    asm("{ .reg .u64 t; cvta.to.shared.u64 t, %1; cvt.u32.u64 %0, t; }" : "=r"(a) : "l"(p));
    return a;
}
__device__ __forceinline__ void cpa16(uint32_t s, const void* g) {
    asm volatile("cp.async.cg.shared.global [%0], [%1], 16;" :: "r"(s), "l"(g));
}
__device__ __forceinline__ void cp_commit() { asm volatile("cp.async.commit_group;" ::); }
template<int N> __device__ __forceinline__ void cp_wait() {
    asm volatile("cp.async.wait_group %0;" :: "n"(N));
}
__device__ __forceinline__ void mma16(float* c, const uint32_t* a, const uint32_t* b) {
    asm volatile(
        "mma.sync.aligned.m16n8k16.row.col.f32.f16.f16.f32 "
        "{%0,%1,%2,%3},{%4,%5,%6,%7},{%8,%9},{%0,%1,%2,%3};"
        : "+f"(c[0]), "+f"(c[1]), "+f"(c[2]), "+f"(c[3])
        : "r"(a[0]), "r"(a[1]), "r"(a[2]), "r"(a[3]), "r"(b[0]), "r"(b[1]));
}
__device__ __forceinline__ uint32_t packh2(float a, float b) {
    __half2 h = __floats2half2_rn(a, b);
    return *(uint32_t*)&h;
}

// ---------------- fp16 mma GEMM: C[M,N] = A[M,K] @ BT[N,K]^T (+RES), fp32 out ----------------
// BM=128, BN=256, BK=64 halves, 3-stage cp.async, 8 warps x (64x64 tile).
// Smem stride 72 halves (36 words): fragment loads hit banks (4g+t)%32 -> conflict-free.
#define BM      128
#define BN      256
#define BKH     64
#define NSTAGE  3
#define HSTRW   36                         // stride in 32-bit words (72 halves)
#define ATILEW  (BM * HSTRW)               // 4608 words
#define BTILEW  (BN * HSTRW)               // 9216 words
#define STAGEW  (ATILEW + BTILEW)          // 13824 words
#define GEMM_SMEM (NSTAGE * STAGEW * 4)    // 165888 B

__global__ __launch_bounds__(256, 1) void gemm_h(
    int M, int N, int K,
    const __half* __restrict__ A, const __half* __restrict__ BT,
    const float* __restrict__ RES, float* __restrict__ C)
{
    extern __shared__ uint32_t smw[];
    const int tid = threadIdx.x;
    const int wid = tid >> 5, lane = tid & 31;
    const int g = lane >> 2, t = lane & 3;
    const int bm0 = blockIdx.y * BM, bn0 = blockIdx.x * BN;
    const int wm0 = (wid & 1) * 64;
    const int wn0 = (wid >> 1) * 64;

    float acc[4][8][4];
    #pragma unroll
    for (int mi = 0; mi < 4; mi++)
        #pragma unroll
        for (int ni = 0; ni < 8; ni++)
            #pragma unroll
            for (int u = 0; u < 4; u++) acc[mi][ni][u] = 0.f;

    const int NC = K / BKH;

    auto issue = [&](int j) {
        uint32_t* st = smw + (j % NSTAGE) * STAGEW;
        const int k0 = j * BKH;
        #pragma unroll
        for (int i = 0; i < 4; i++) {               // A: 1024 x 16B (8 halves)
            const int idx = tid + i * 256;
            const int r = idx >> 3, f = idx & 7;
            cpa16(s2u(st + r * HSTRW + f * 4), A + (size_t)(bm0 + r) * K + k0 + f * 8);
        }
        uint32_t* stb = st + ATILEW;
        #pragma unroll
        for (int i = 0; i < 8; i++) {               // B: 2048 x 16B
            const int idx = tid + i * 256;
            const int r = idx >> 3, f = idx & 7;
            cpa16(s2u(stb + r * HSTRW + f * 4), BT + (size_t)(bn0 + r) * K + k0 + f * 8);
        }
        cp_commit();
    };

    for (int j = 0; j < NSTAGE; j++) issue(j);      // NC >= NSTAGE for all shapes here

    for (int c = 0; c < NC; c++) {
        const int inflight_after = (c + NSTAGE <= NC ? c + NSTAGE : NC) - (c + 1);
        if (inflight_after >= 2)      cp_wait<2>();
        else if (inflight_after == 1) cp_wait<1>();
        else                          cp_wait<0>();
        __syncthreads();

        const uint32_t* sa = smw + (c % NSTAGE) * STAGEW;
        const uint32_t* sb = sa + ATILEW;
        #pragma unroll
        for (int kk = 0; kk < 4; kk++) {            // 4 x k16 steps (BK=64 halves)
            const int kw = kk * 8;                  // word offset (16 halves)
            uint32_t af[4][4];
            #pragma unroll
            for (int mi = 0; mi < 4; mi++) {
                const uint32_t* p = sa + (wm0 + mi * 16 + g) * HSTRW + kw + t;
                af[mi][0] = p[0];
                af[mi][1] = p[8 * HSTRW];
                af[mi][2] = p[4];
                af[mi][3] = p[8 * HSTRW + 4];
            }
            uint32_t bf[8][2];
            #pragma unroll
            for (int ni = 0; ni < 8; ni++) {
                const uint32_t* p = sb + (wn0 + ni * 8 + g) * HSTRW + kw + t;
                bf[ni][0] = p[0];
                bf[ni][1] = p[4];
            }
            #pragma unroll
            for (int mi = 0; mi < 4; mi++)
                #pragma unroll
                for (int ni = 0; ni < 8; ni++)
                    mma16(acc[mi][ni], af[mi], bf[ni]);
        }
        __syncthreads();
        if (c + NSTAGE < NC) issue(c + NSTAGE);
    }

    #pragma unroll
    for (int mi = 0; mi < 4; mi++) {
        const int row0 = bm0 + wm0 + mi * 16 + g;
        #pragma unroll
        for (int ni = 0; ni < 8; ni++) {
            const int col = bn0 + wn0 + ni * 8 + 2 * t;
            float2 d0 = make_float2(acc[mi][ni][0], acc[mi][ni][1]);
            float2 d1 = make_float2(acc[mi][ni][2], acc[mi][ni][3]);
            if (RES) {
                float2 r0 = *(const float2*)(RES + (size_t)row0 * N + col);
                float2 r1 = *(const float2*)(RES + (size_t)(row0 + 8) * N + col);
                d0.x += r0.x; d0.y += r0.y;
                d1.x += r1.x; d1.y += r1.y;
            }
            *(float2*)(C + (size_t)row0 * N + col)       = d0;
            *(float2*)(C + (size_t)(row0 + 8) * N + col) = d1;
        }
    }
}

// ---------------- transpose + fp16 round: out[C,R] = h(in[R,C]^T) ----------------
__global__ __launch_bounds__(256) void transpose_h_kernel(
    const float* __restrict__ in, __half* __restrict__ out, int R, int C)
{
    __shared__ float t[32][33];
    const int bx = blockIdx.x * 32;
    const int by = blockIdx.y * 32;
    const int x = threadIdx.x, y = threadIdx.y;  // (32, 8)
    #pragma unroll
    for (int j = 0; j < 32; j += 8)
        t[y + j][x] = in[(size_t)(by + y + j) * C + bx + x];
    __syncthreads();
    #pragma unroll
    for (int j = 0; j < 32; j += 8)
        out[(size_t)(bx + y + j) * R + by + x] = __float2half_rn(t[x][y + j]);
}

// ---------------- RMSNorm (fp16 output) ----------------
__global__ __launch_bounds__(256) void rmsnorm_h_kernel(
    const float* __restrict__ x, const float* __restrict__ w, __half* __restrict__ out)
{
    const int row = blockIdx.x;
    const float* xr = x + (size_t)row * HID;
    float ss = 0.f;
    for (int i = threadIdx.x; i < 512; i += 256) {
        float4 v = ((const float4*)xr)[i];
        ss += v.x*v.x + v.y*v.y + v.z*v.z + v.w*v.w;
    }
    #pragma unroll
    for (int o = 16; o > 0; o >>= 1) ss += __shfl_xor_sync(0xffffffffu, ss, o);
    __shared__ float red[8];
    if ((threadIdx.x & 31) == 0) red[threadIdx.x >> 5] = ss;
    __syncthreads();
    float tot = red[0];
    #pragma unroll
    for (int i = 1; i < 8; i++) tot += red[i];
    const float rs = rsqrtf(tot / (float)HID + 1e-6f);
    uint2* orow = (uint2*)(out + (size_t)row * HID);
    for (int i = threadIdx.x; i < 512; i += 256) {
        float4 v = ((const float4*)xr)[i];
        float4 ww = ((const float4*)w)[i];
        uint2 o;
        o.x = packh2(v.x * rs * ww.x, v.y * rs * ww.y);
        o.y = packh2(v.z * rs * ww.z, v.w * rs * ww.w);
        orow[i] = o;
    }
}

// ---------------- RoPE -> fp16 q,k ; fp16 convert v ----------------
__global__ void rope_half_kernel(
    const float* __restrict__ q, const float* __restrict__ k, const float* __restrict__ v,
    __half* __restrict__ qh, __half* __restrict__ kh, __half* __restrict__ vh)
{
    const int NQ = TOK * NH * (HD / 2);      // 4M rotation pairs
    const int NK = TOK * NKV * (HD / 2);     // 1M
    const int NV2 = TOK * NKV * HD / 2;      // 1M half2 conversions
    int idx = blockIdx.x * blockDim.x + threadIdx.x;
    if (idx < NQ + NK) {
        const float* p; __half* ph;
        int token, i;
        if (idx < NQ) {
            token = idx >> 10;
            const int rem = idx & 1023;
            const int head = rem >> 5;
            i = rem & 31;
            p  = q  + (size_t)token * (NH * HD) + head * HD;
            ph = qh + (size_t)token * (NH * HD) + head * HD;
        } else {
            idx -= NQ;
            token = idx >> 8;
            const int rem = idx & 255;
            const int head = rem >> 5;
            i = rem & 31;
            p  = k  + (size_t)token * (NKV * HD) + head * HD;
            ph = kh + (size_t)token * (NKV * HD) + head * HD;
        }
        const int pos = token & (SS - 1);
        const float inv_freq = powf(10000.0f, -(float)i / 32.0f);
        const float ang = (float)pos * inv_freq;
        const float c = cosf(ang), s = sinf(ang);
        const float x1 = p[i], x2 = p[i + 32];
        ph[i]      = __float2half_rn(x1 * c - x2 * s);
        ph[i + 32] = __float2half_rn(x2 * c + x1 * s);
    } else {
        idx -= (NQ + NK);
        if (idx >= NV2) return;
        float2 vv = ((const float2*)v)[idx];
        ((uint32_t*)vh)[idx] = packh2(vv.x, vv.y);
    }
}

// ---------------- Flash attention, fp16 mma (causal, GQA rep=4) ----------------
// grid (S/64, NH, B); 128 threads (4 warps); warp w owns q rows [w*16, w*16+16).
__global__ __launch_bounds__(128) void flash_attn_mma_kernel(
    const __half* __restrict__ Qh, const __half* __restrict__ Kh,
    const __half* __restrict__ Vh, __half* __restrict__ Oh)
{
    __shared__ uint32_t Kw[64 * 36];   // [token][72 halves] row-major
    __shared__ uint32_t Vw[64 * 36];   // [dim][72 halves] transposed, XOR-swizzled
    const int b = blockIdx.z, h = blockIdx.y, qt = blockIdx.x;
    const int kvh = h >> 2;
    const int tid = threadIdx.x;
    const int w = tid >> 5, lane = tid & 31;
    const int g = lane >> 2, t = lane & 3;
    const int q0 = qt * 64;
    const size_t tokbase = (size_t)b * SS;

    // Q fragments: 4 k-steps x 4 regs, loaded straight from gmem (half2 = b32)
    uint32_t aq[4][4];
    {
        const __half* qpg  = Qh + ((tokbase + q0 + w * 16 + g)     * NH + h) * HD;
        const __half* qpg8 = Qh + ((tokbase + q0 + w * 16 + g + 8) * NH + h) * HD;
        #pragma unroll
        for (int kk = 0; kk < 4; kk++) {
            aq[kk][0] = *(const uint32_t*)(qpg  + kk * 16 + 2 * t);
            aq[kk][1] = *(const uint32_t*)(qpg8 + kk * 16 + 2 * t);
            aq[kk][2] = *(const uint32_t*)(qpg  + kk * 16 + 8 + 2 * t);
            aq[kk][3] = *(const uint32_t*)(qpg8 + kk * 16 + 8 + 2 * t);
        }
    }

    float accO[8][4];
    #pragma unroll
    for (int ni = 0; ni < 8; ni++)
        #pragma unroll
        for (int u = 0; u < 4; u++) accO[ni][u] = 0.f;
    float m0 = -1e30f, m1 = -1e30f, l0 = 0.f, l1 = 0.f;
    const int qrow0 = q0 + w * 16 + g;
    const int qrow1 = qrow0 + 8;

    for (int kt = 0; kt <= qt; kt++) {
        __syncthreads();
        const size_t kg = (tokbase + kt * 64) * (NKV * HD) + kvh * HD;
        #pragma unroll
        for (int it = 0; it < 4; it++) {
            const int idx = tid + it * 128;          // 0..511
            const int row = idx >> 3, f = idx & 7;
            *(uint4*)&Kw[row * 36 + f * 4] = *(const uint4*)(Kh + kg + (size_t)row * (NKV * HD) + f * 8);
            uint4 vv4 = *(const uint4*)(Vh + kg + (size_t)row * (NKV * HD) + f * 8);
            const __half* hv = (const __half*)&vv4;
            #pragma unroll
            for (int j = 0; j < 8; j++) {
                const int d = f * 8 + j;
                ((__half*)Vw)[d * 72 + (row ^ ((d >> 3) << 3))] = hv[j];
            }
        }
        __syncthreads();

        // S = Q @ K^T  (scores for this warp: 16 rows x 64 kv)
        float sc[8][4];
        #pragma unroll
        for (int ni = 0; ni < 8; ni++) {
            sc[ni][0] = sc[ni][1] = sc[ni][2] = sc[ni][3] = 0.f;
            const uint32_t* kp = Kw + (ni * 8 + g) * 36 + t;
            #pragma unroll
            for (int kk = 0; kk < 4; kk++) {
                uint32_t bk[2] = { kp[kk * 8], kp[kk * 8 + 4] };
                mma16(sc[ni], aq[kk], bk);
            }
        }
        // scale + causal mask
        const int kb = kt * 64;
        #pragma unroll
        for (int ni = 0; ni < 8; ni++) {
            const int col = kb + ni * 8 + 2 * t;
            sc[ni][0] = (col     <= qrow0) ? sc[ni][0] * 0.125f : -1e30f;
            sc[ni][1] = (col + 1 <= qrow0) ? sc[ni][1] * 0.125f : -1e30f;
            sc[ni][2] = (col     <= qrow1) ? sc[ni][2] * 0.125f : -1e30f;
            sc[ni][3] = (col + 1 <= qrow1) ? sc[ni][3] * 0.125f : -1e30f;
        }
        // online softmax (rows g / g+8; quad lanes share a row)
        float mt0 = -1e30f, mt1 = -1e30f;
        #pragma unroll
        for (int ni = 0; ni < 8; ni++) {
            mt0 = fmaxf(mt0, fmaxf(sc[ni][0], sc[ni][1]));
            mt1 = fmaxf(mt1, fmaxf(sc[ni][2], sc[ni][3]));
        }
        mt0 = fmaxf(mt0, __shfl_xor_sync(0xffffffffu, mt0, 1));
        mt0 = fmaxf(mt0, __shfl_xor_sync(0xffffffffu, mt0, 2));
        mt1 = fmaxf(mt1, __shfl_xor_sync(0xffffffffu, mt1, 1));
        mt1 = fmaxf(mt1, __shfl_xor_sync(0xffffffffu, mt1, 2));
        const float mn0 = fmaxf(m0, mt0), mn1 = fmaxf(m1, mt1);
        const float sc0 = __expf(m0 - mn0), sc1 = __expf(m1 - mn1);
        m0 = mn0; m1 = mn1;
        float ls0 = 0.f, ls1 = 0.f;
        #pragma unroll
        for (int ni = 0; ni < 8; ni++) {
            sc[ni][0] = __expf(sc[ni][0] - m0);
            sc[ni][1] = __expf(sc[ni][1] - m0);
            sc[ni][2] = __expf(sc[ni][2] - m1);
            sc[ni][3] = __expf(sc[ni][3] - m1);
            ls0 += sc[ni][0] + sc[ni][1];
            ls1 += sc[ni][2] + sc[ni][3];
        }
        l0 = l0 * sc0 + ls0;
        l1 = l1 * sc1 + ls1;
        #pragma unroll
        for (int ni = 0; ni < 8; ni++) {
            accO[ni][0] *= sc0; accO[ni][1] *= sc0;
            accO[ni][2] *= sc1; accO[ni][3] *= sc1;
        }
        // O += P @ V   (P halves from score frags; V^T swizzled in smem)
        #pragma unroll
        for (int j = 0; j < 4; j++) {               // kv k-groups of 16
            uint32_t ap[4];
            ap[0] = packh2(sc[2*j][0],   sc[2*j][1]);
            ap[1] = packh2(sc[2*j][2],   sc[2*j][3]);
            ap[2] = packh2(sc[2*j+1][0], sc[2*j+1][1]);
            ap[3] = packh2(sc[2*j+1][2], sc[2*j+1][3]);
            #pragma unroll
            for (int ni = 0; ni < 8; ni++) {        // output dim groups of 8
                const int d0 = ni * 8 + g;
                const int h0 = (16 * j + 2 * t) ^ (8 * ni);
                const int h1 = (16 * j + 8 + 2 * t) ^ (8 * ni);
                uint32_t bv[2] = { Vw[d0 * 36 + (h0 >> 1)], Vw[d0 * 36 + (h1 >> 1)] };
                mma16(accO[ni], ap, bv);
            }
        }
    }
    l0 += __shfl_xor_sync(0xffffffffu, l0, 1);
    l0 += __shfl_xor_sync(0xffffffffu, l0, 2);
    l1 += __shfl_xor_sync(0xffffffffu, l1, 1);
    l1 += __shfl_xor_sync(0xffffffffu, l1, 2);
    const float i0 = 1.f / l0, i1 = 1.f / l1;
    __half* op0 = Oh + ((tokbase + qrow0) * NH + h) * HD;
    __half* op1 = Oh + ((tokbase + qrow1) * NH + h) * HD;
    #pragma unroll
    for (int ni = 0; ni < 8; ni++) {
        const int col = ni * 8 + 2 * t;
        *(uint32_t*)(op0 + col) = packh2(accO[ni][0] * i0, accO[ni][1] * i0);
        *(uint32_t*)(op1 + col) = packh2(accO[ni][2] * i1, accO[ni][3] * i1);
    }
}

// ---------------- SwiGLU: gateh <- h(silu(gate) * up) ----------------
__global__ void swiglu_h_kernel(const float* __restrict__ gate, const float* __restrict__ up,
                                __half* __restrict__ gh)
{
    const int idx = blockIdx.x * blockDim.x + threadIdx.x;
    const int n4 = (TOK * FF) / 4;
    if (idx >= n4) return;
    float4 g = ((const float4*)gate)[idx];
    float4 u = ((const float4*)up)[idx];
    uint2 o;
    o.x = packh2(g.x / (1.f + __expf(-g.x)) * u.x, g.y / (1.f + __expf(-g.y)) * u.y);
    o.y = packh2(g.z / (1.f + __expf(-g.z)) * u.z, g.w / (1.f + __expf(-g.w)) * u.w);
    ((uint2*)gh)[idx] = o;
}

// ---------------- launch ----------------
extern "C" void kernel_launch(void* const* d_in, const int* in_sizes, int n_in,
                              void* d_out, int out_size)
{
    const float* hs     = (const float*)d_in[0];
    const float* wq     = (const float*)d_in[1];
    const float* wk     = (const float*)d_in[2];
    const float* wv     = (const float*)d_in[3];
    const float* wo     = (const float*)d_in[4];
    const float* w_gate = (const float*)d_in[5];
    const float* w_up   = (const float*)d_in[6];
    const float* w_down = (const float*)d_in[7];
    const float* norm1  = (const float*)d_in[8];
    const float* norm2  = (const float*)d_in[9];
    float* out = (float*)d_out;

    float *q, *k, *v, *hid, *gate, *up;
    __half *xnh, *qh, *kh, *vh, *attnh, *ynh, *gateh;
    __half *wqT, *wkT, *wvT, *woT, *wgT, *wuT, *wdT;
    cudaGetSymbolAddress((void**)&q,     g_q);
    cudaGetSymbolAddress((void**)&k,     g_k);
    cudaGetSymbolAddress((void**)&v,     g_v);
    cudaGetSymbolAddress((void**)&hid,   g_hid);
    cudaGetSymbolAddress((void**)&gate,  g_gate);
    cudaGetSymbolAddress((void**)&up,    g_up);
    cudaGetSymbolAddress((void**)&xnh,   g_xnh);
    cudaGetSymbolAddress((void**)&qh,    g_qh);
    cudaGetSymbolAddress((void**)&kh,    g_kh);
    cudaGetSymbolAddress((void**)&vh,    g_vh);
    cudaGetSymbolAddress((void**)&attnh, g_attnh);
    cudaGetSymbolAddress((void**)&ynh,   g_ynh);
    cudaGetSymbolAddress((void**)&gateh, g_gateh);
    cudaGetSymbolAddress((void**)&wqT,   g_wqT);
    cudaGetSymbolAddress((void**)&wkT,   g_wkT);
    cudaGetSymbolAddress((void**)&wvT,   g_wvT);
    cudaGetSymbolAddress((void**)&woT,   g_woT);
    cudaGetSymbolAddress((void**)&wgT,   g_wgT);
    cudaGetSymbolAddress((void**)&wuT,   g_wuT);
    cudaGetSymbolAddress((void**)&wdT,   g_wdT);

    cudaFuncSetAttribute(gemm_h, cudaFuncAttributeMaxDynamicSharedMemorySize, GEMM_SMEM);

    const dim3 tb(32, 8);
    transpose_h_kernel<<<dim3(2048/32, 2048/32), tb>>>(wq,     wqT, 2048, 2048);
    transpose_h_kernel<<<dim3( 512/32, 2048/32), tb>>>(wk,     wkT, 2048,  512);
    transpose_h_kernel<<<dim3( 512/32, 2048/32), tb>>>(wv,     wvT, 2048,  512);
    transpose_h_kernel<<<dim3(2048/32, 2048/32), tb>>>(wo,     woT, 2048, 2048);
    transpose_h_kernel<<<dim3(  FF/32, 2048/32), tb>>>(w_gate, wgT, 2048,   FF);
    transpose_h_kernel<<<dim3(  FF/32, 2048/32), tb>>>(w_up,   wuT, 2048,   FF);
    transpose_h_kernel<<<dim3(2048/32,   FF/32), tb>>>(w_down, wdT,   FF, 2048);

    // 1) pre-norm -> fp16
    rmsnorm_h_kernel<<<TOK, 256>>>(hs, norm1, xnh);
    // 2) QKV projections (fp16 mma, fp32 out)
    gemm_h<<<dim3(2048/BN, TOK/BM), 256, GEMM_SMEM>>>(TOK, 2048, HID, xnh, wqT, nullptr, q);
    gemm_h<<<dim3( 512/BN, TOK/BM), 256, GEMM_SMEM>>>(TOK,  512, HID, xnh, wkT, nullptr, k);
    gemm_h<<<dim3( 512/BN, TOK/BM), 256, GEMM_SMEM>>>(TOK,  512, HID, xnh, wvT, nullptr, v);
    // 3) RoPE -> fp16 q,k ; convert v -> fp16
    {
        const int total = TOK*NH*(HD/2) + TOK*NKV*(HD/2) + TOK*NKV*HD/2;
        rope_half_kernel<<<(total + 255) / 256, 256>>>(q, k, v, qh, kh, vh);
    }
    // 4) causal GQA flash attention (fp16 mma)
    flash_attn_mma_kernel<<<dim3(SS/64, NH, BB), 128>>>(qh, kh, vh, attnh);
    // 5) output projection + residual
    gemm_h<<<dim3(2048/BN, TOK/BM), 256, GEMM_SMEM>>>(TOK, 2048, NH*HD, attnh, woT, hs, hid);
    // 6) post-norm -> fp16
    rmsnorm_h_kernel<<<TOK, 256>>>(hid, norm2, ynh);
    // 7) gate/up projections
    gemm_h<<<dim3(FF/BN, TOK/BM), 256, GEMM_SMEM>>>(TOK, FF, HID, ynh, wgT, nullptr, gate);
    gemm_h<<<dim3(FF/BN, TOK/BM), 256, GEMM_SMEM>>>(TOK, FF, HID, ynh, wuT, nullptr, up);
    // 8) SwiGLU -> fp16
    swiglu_h_kernel<<<((TOK*FF/4) + 255) / 256, 256>>>(gate, up, gateh);
    // 9) down projection + residual -> fp32 output
    gemm_h<<<dim3(HID/BN, TOK/BM), 256, GEMM_SMEM>>>(TOK, HID, FF, gateh, wdT, hid, out);
}

// round 8
// speedup vs baseline: 9.2011x; 1.0527x over previous
#include <cuda_runtime.h>
#include <cuda_fp16.h>
#include <cstdint>

// Problem constants
#define HID   2048
#define NH    32
#define NKV   8
#define HD    64
#define FF    5632
#define BB    2
#define SS    2048
#define TOK   (BB*SS)           // 4096
#define NQKV  3072              // 2048 q + 512 k + 512 v
#define KOFF  2048
#define VOFF  2560

// ---------------- scratch (alloc-free: __device__ globals) ----------------
__device__ float  g_hid [TOK * HID];
__device__ __half g_xnh [TOK * HID];
__device__ __half g_qkvh[TOK * NQKV];
__device__ __half g_attnh[TOK * HID];
__device__ __half g_ynh [TOK * HID];
__device__ __half g_gateh[TOK * FF];
// transposed/interleaved (N-major, K-contiguous) fp16 weights
__device__ __half g_wqkvT[NQKV * HID];       // rows: 0..2047 wq^T, 2048..2559 wk^T, 2560..3071 wv^T
__device__ __half g_woT  [HID * HID];
__device__ __half g_wguT [2 * FF * HID];     // row 2n = wg^T[n], row 2n+1 = wu^T[n]
__device__ __half g_wdT  [HID * FF];

// ---------------- helpers ----------------
__device__ __forceinline__ uint32_t s2u(const void* p) {
    uint32_t a;
    asm("{ .reg .u64 t; cvta.to.shared.u64 t, %1; cvt.u32.u64 %0, t; }" : "=r"(a) : "l"(p));
    return a;
}
__device__ __forceinline__ void cpa16(uint32_t s, const void* g) {
    asm volatile("cp.async.cg.shared.global [%0], [%1], 16;" :: "r"(s), "l"(g));
}
__device__ __forceinline__ void cp_commit() { asm volatile("cp.async.commit_group;" ::); }
template<int N> __device__ __forceinline__ void cp_wait() {
    asm volatile("cp.async.wait_group %0;" :: "n"(N));
}
__device__ __forceinline__ void mma16(float* c, const uint32_t* a, const uint32_t* b) {
    asm volatile(
        "mma.sync.aligned.m16n8k16.row.col.f32.f16.f16.f32 "
        "{%0,%1,%2,%3},{%4,%5,%6,%7},{%8,%9},{%0,%1,%2,%3};"
        : "+f"(c[0]), "+f"(c[1]), "+f"(c[2]), "+f"(c[3])
        : "r"(a[0]), "r"(a[1]), "r"(a[2]), "r"(a[3]), "r"(b[0]), "r"(b[1]));
}
__device__ __forceinline__ void ldsm4t(uint32_t* r, uint32_t saddr) {
    asm volatile("ldmatrix.sync.aligned.m8n8.x4.trans.shared.b16 {%0,%1,%2,%3}, [%4];"
        : "=r"(r[0]), "=r"(r[1]), "=r"(r[2]), "=r"(r[3]) : "r"(saddr));
}
__device__ __forceinline__ uint32_t packh2(float a, float b) {
    __half2 h = __floats2half2_rn(a, b);
    return *(uint32_t*)&h;
}

// ---------------- fp16 mma GEMM core, epilogue selected by MODE ----------------
// MODE 0: fp32 out (+optional RES).   Cout = float*
// MODE 1: QKV fused RoPE, fp16 out -> qkvh [TOK][3072]
// MODE 2: gate/up interleaved, swiglu epilogue, fp16 out -> gateh [TOK][FF]
#define BM      128
#define BN      256
#define BKH     64
#define NSTAGE  3
#define HSTRW   36                         // row stride in 32-bit words (72 halves)
#define ATILEW  (BM * HSTRW)
#define BTILEW  (BN * HSTRW)
#define STAGEW  (ATILEW + BTILEW)
#define GEMM_SMEM (NSTAGE * STAGEW * 4)    // 165888 B

template<int MODE>
__global__ __launch_bounds__(256, 1) void gemm_h(
    int M, int N, int K,
    const __half* __restrict__ A, const __half* __restrict__ BT,
    const float* __restrict__ RES, void* __restrict__ Cout)
{
    extern __shared__ uint32_t smw[];
    const int tid = threadIdx.x;
    const int wid = tid >> 5, lane = tid & 31;
    const int g = lane >> 2, t = lane & 3;
    const int bm0 = blockIdx.y * BM, bn0 = blockIdx.x * BN;
    const int wm0 = (wid & 1) * 64;
    const int wn0 = (wid >> 1) * 64;

    float acc[4][8][4];
    #pragma unroll
    for (int mi = 0; mi < 4; mi++)
        #pragma unroll
        for (int ni = 0; ni < 8; ni++)
            #pragma unroll
            for (int u = 0; u < 4; u++) acc[mi][ni][u] = 0.f;

    const int NC = K / BKH;

    auto issue = [&](int j) {
        uint32_t* st = smw + (j % NSTAGE) * STAGEW;
        const int k0 = j * BKH;
        #pragma unroll
        for (int i = 0; i < 4; i++) {
            const int idx = tid + i * 256;
            const int r = idx >> 3, f = idx & 7;
            cpa16(s2u(st + r * HSTRW + f * 4), A + (size_t)(bm0 + r) * K + k0 + f * 8);
        }
        uint32_t* stb = st + ATILEW;
        #pragma unroll
        for (int i = 0; i < 8; i++) {
            const int idx = tid + i * 256;
            const int r = idx >> 3, f = idx & 7;
            cpa16(s2u(stb + r * HSTRW + f * 4), BT + (size_t)(bn0 + r) * K + k0 + f * 8);
        }
        cp_commit();
    };

    for (int j = 0; j < NSTAGE; j++) issue(j);

    for (int c = 0; c < NC; c++) {
        const int inflight_after = (c + NSTAGE <= NC ? c + NSTAGE : NC) - (c + 1);
        if (inflight_after >= 2)      cp_wait<2>();
        else if (inflight_after == 1) cp_wait<1>();
        else                          cp_wait<0>();
        __syncthreads();

        const uint32_t* sa = smw + (c % NSTAGE) * STAGEW;
        const uint32_t* sb = sa + ATILEW;
        #pragma unroll
        for (int kk = 0; kk < 4; kk++) {
            const int kw = kk * 8;
            uint32_t af[4][4];
            #pragma unroll
            for (int mi = 0; mi < 4; mi++) {
                const uint32_t* p = sa + (wm0 + mi * 16 + g) * HSTRW + kw + t;
                af[mi][0] = p[0];
                af[mi][1] = p[8 * HSTRW];
                af[mi][2] = p[4];
                af[mi][3] = p[8 * HSTRW + 4];
            }
            uint32_t bf[8][2];
            #pragma unroll
            for (int ni = 0; ni < 8; ni++) {
                const uint32_t* p = sb + (wn0 + ni * 8 + g) * HSTRW + kw + t;
                bf[ni][0] = p[0];
                bf[ni][1] = p[4];
            }
            #pragma unroll
            for (int mi = 0; mi < 4; mi++)
                #pragma unroll
                for (int ni = 0; ni < 8; ni++)
                    mma16(acc[mi][ni], af[mi], bf[ni]);
        }
        __syncthreads();
        if (c + NSTAGE < NC) issue(c + NSTAGE);
    }

    // ---------------- epilogues ----------------
    if (MODE == 0) {
        float* C = (float*)Cout;
        #pragma unroll
        for (int mi = 0; mi < 4; mi++) {
            const int row0 = bm0 + wm0 + mi * 16 + g;
            #pragma unroll
            for (int ni = 0; ni < 8; ni++) {
                const int col = bn0 + wn0 + ni * 8 + 2 * t;
                float2 d0 = make_float2(acc[mi][ni][0], acc[mi][ni][1]);
                float2 d1 = make_float2(acc[mi][ni][2], acc[mi][ni][3]);
                if (RES) {
                    float2 r0 = *(const float2*)(RES + (size_t)row0 * N + col);
                    float2 r1 = *(const float2*)(RES + (size_t)(row0 + 8) * N + col);
                    d0.x += r0.x; d0.y += r0.y;
                    d1.x += r1.x; d1.y += r1.y;
                }
                *(float2*)(C + (size_t)row0 * N + col)       = d0;
                *(float2*)(C + (size_t)(row0 + 8) * N + col) = d1;
            }
        }
    } else if (MODE == 1) {
        __half* O = (__half*)Cout;
        const int colbase = bn0 + wn0;           // 64-aligned => single head / segment
        if (colbase >= VOFF) {                   // V: plain fp16 convert
            #pragma unroll
            for (int mi = 0; mi < 4; mi++) {
                const int r0 = bm0 + wm0 + mi * 16 + g;
                __half* p0 = O + (size_t)r0 * NQKV;
                __half* p1 = O + (size_t)(r0 + 8) * NQKV;
                #pragma unroll
                for (int ni = 0; ni < 8; ni++) {
                    const int col = colbase + ni * 8 + 2 * t;
                    *(uint32_t*)(p0 + col) = packh2(acc[mi][ni][0], acc[mi][ni][1]);
                    *(uint32_t*)(p1 + col) = packh2(acc[mi][ni][2], acc[mi][ni][3]);
                }
            }
        } else {                                 // Q or K: fused RoPE
            float invf[4][2];
            #pragma unroll
            for (int ni = 0; ni < 4; ni++)
                #pragma unroll
                for (int u = 0; u < 2; u++) {
                    const int i = ni * 8 + 2 * t + u;
                    invf[ni][u] = powf(10000.0f, -(float)i / 32.0f);
                }
            #pragma unroll
            for (int mi = 0; mi < 4; mi++) {
                const int r0 = bm0 + wm0 + mi * 16 + g;
                const int r1 = r0 + 8;
                const float pos0 = (float)(r0 & (SS - 1));
                const float pos1 = (float)(r1 & (SS - 1));
                __half* p0 = O + (size_t)r0 * NQKV;
                __half* p1 = O + (size_t)r1 * NQKV;
                #pragma unroll
                for (int ni = 0; ni < 4; ni++) {
                    float lo0[2], hi0[2], lo1[2], hi1[2];
                    #pragma unroll
                    for (int u = 0; u < 2; u++) {
                        float s0, c0, s1, c1;
                        sincosf(pos0 * invf[ni][u], &s0, &c0);
                        sincosf(pos1 * invf[ni][u], &s1, &c1);
                        const float x1a = acc[mi][ni][u],     x2a = acc[mi][ni + 4][u];
                        const float x1b = acc[mi][ni][u + 2], x2b = acc[mi][ni + 4][u + 2];
                        lo0[u] = x1a * c0 - x2a * s0;  hi0[u] = x2a * c0 + x1a * s0;
                        lo1[u] = x1b * c1 - x2b * s1;  hi1[u] = x2b * c1 + x1b * s1;
                    }
                    const int col = colbase + ni * 8 + 2 * t;
                    *(uint32_t*)(p0 + col)      = packh2(lo0[0], lo0[1]);
                    *(uint32_t*)(p0 + col + 32) = packh2(hi0[0], hi0[1]);
                    *(uint32_t*)(p1 + col)      = packh2(lo1[0], lo1[1]);
                    *(uint32_t*)(p1 + col + 32) = packh2(hi1[0], hi1[1]);
                }
            }
        }
    } else {                                     // MODE 2: swiglu pairs (even=gate, odd=up)
        __half* O = (__half*)Cout;
        #pragma unroll
        for (int mi = 0; mi < 4; mi++) {
            const int r0 = bm0 + wm0 + mi * 16 + g;
            #pragma unroll
            for (int ni = 0; ni < 8; ni++) {
                const int c2 = (bn0 + wn0 + ni * 8) / 2 + t;
                const float ga = acc[mi][ni][0], ua = acc[mi][ni][1];
                const float gb = acc[mi][ni][2], ub = acc[mi][ni][3];
                O[(size_t)r0 * FF + c2]       = __float2half_rn(ga / (1.f + __expf(-ga)) * ua);
                O[(size_t)(r0 + 8) * FF + c2] = __float2half_rn(gb / (1.f + __expf(-gb)) * ub);
            }
        }
    }
}

// ---------------- transpose + fp16: out[(c*mul+add)][r] = h(in[r][c]) ----------------
__global__ __launch_bounds__(256) void transpose_h_kernel(
    const float* __restrict__ in, __half* __restrict__ out, int R, int C, int mul, int add)
{
    __shared__ float t[32][33];
    const int bx = blockIdx.x * 32;
    const int by = blockIdx.y * 32;
    const int x = threadIdx.x, y = threadIdx.y;  // (32, 8)
    #pragma unroll
    for (int j = 0; j < 32; j += 8)
        t[y + j][x] = in[(size_t)(by + y + j) * C + bx + x];
    __syncthreads();
    #pragma unroll
    for (int j = 0; j < 32; j += 8)
        out[((size_t)(bx + y + j) * mul + add) * R + by + x] = __float2half_rn(t[x][y + j]);
}

// ---------------- RMSNorm (fp16 output) ----------------
__global__ __launch_bounds__(256) void rmsnorm_h_kernel(
    const float* __restrict__ x, const float* __restrict__ w, __half* __restrict__ out)
{
    const int row = blockIdx.x;
    const float* xr = x + (size_t)row * HID;
    float ss = 0.f;
    for (int i = threadIdx.x; i < 512; i += 256) {
        float4 v = ((const float4*)xr)[i];
        ss += v.x*v.x + v.y*v.y + v.z*v.z + v.w*v.w;
    }
    #pragma unroll
    for (int o = 16; o > 0; o >>= 1) ss += __shfl_xor_sync(0xffffffffu, ss, o);
    __shared__ float red[8];
    if ((threadIdx.x & 31) == 0) red[threadIdx.x >> 5] = ss;
    __syncthreads();
    float tot = red[0];
    #pragma unroll
    for (int i = 1; i < 8; i++) tot += red[i];
    const float rs = rsqrtf(tot / (float)HID + 1e-6f);
    uint2* orow = (uint2*)(out + (size_t)row * HID);
    for (int i = threadIdx.x; i < 512; i += 256) {
        float4 v = ((const float4*)xr)[i];
        float4 ww = ((const float4*)w)[i];
        uint2 o;
        o.x = packh2(v.x * rs * ww.x, v.y * rs * ww.y);
        o.y = packh2(v.z * rs * ww.z, v.w * rs * ww.w);
        orow[i] = o;
    }
}

// ---------------- Flash attention, fp16 mma, qkv packed layout ----------------
// grid (S/64, NH, B); 128 threads (4 warps); warp w owns q rows [w*16, w*16+16).
__global__ __launch_bounds__(128) void flash_attn_mma_kernel(
    const __half* __restrict__ QKV, __half* __restrict__ Oh)
{
    __shared__ uint32_t Kw[64 * 36];   // [token][72 halves] row-major
    __shared__ uint32_t Vw[64 * 36];   // [token][72 halves] row-major (ldmatrix.trans for B)
    const int b = blockIdx.z, h = blockIdx.y, qt = blockIdx.x;
    const int kvh = h >> 2;
    const int tid = threadIdx.x;
    const int w = tid >> 5, lane = tid & 31;
    const int g = lane >> 2, t = lane & 3;
    const int q0 = qt * 64;
    const size_t tokbase = (size_t)b * SS;
    const uint32_t vbase = s2u(Vw);

    uint32_t aq[4][4];
    {
        const __half* qpg  = QKV + (tokbase + q0 + w * 16 + g)     * NQKV + h * HD;
        const __half* qpg8 = QKV + (tokbase + q0 + w * 16 + g + 8) * NQKV + h * HD;
        #pragma unroll
        for (int kk = 0; kk < 4; kk++) {
            aq[kk][0] = *(const uint32_t*)(qpg  + kk * 16 + 2 * t);
            aq[kk][1] = *(const uint32_t*)(qpg8 + kk * 16 + 2 * t);
            aq[kk][2] = *(const uint32_t*)(qpg  + kk * 16 + 8 + 2 * t);
            aq[kk][3] = *(const uint32_t*)(qpg8 + kk * 16 + 8 + 2 * t);
        }
    }

    float accO[8][4];
    #pragma unroll
    for (int ni = 0; ni < 8; ni++)
        #pragma unroll
        for (int u = 0; u < 4; u++) accO[ni][u] = 0.f;
    float m0 = -1e30f, m1 = -1e30f, l0 = 0.f, l1 = 0.f;
    const int qrow0 = q0 + w * 16 + g;
    const int qrow1 = qrow0 + 8;

    for (int kt = 0; kt <= qt; kt++) {
        __syncthreads();
        const __half* Kbase = QKV + (tokbase + kt * 64) * NQKV + KOFF + kvh * HD;
        const __half* Vbase = QKV + (tokbase + kt * 64) * NQKV + VOFF + kvh * HD;
        #pragma unroll
        for (int it = 0; it < 4; it++) {
            const int idx = tid + it * 128;          // 0..511
            const int row = idx >> 3, f = idx & 7;
            *(uint4*)&Kw[row * 36 + f * 4] = *(const uint4*)(Kbase + (size_t)row * NQKV + f * 8);
            *(uint4*)&Vw[row * 36 + f * 4] = *(const uint4*)(Vbase + (size_t)row * NQKV + f * 8);
        }
        __syncthreads();

        // S = Q @ K^T
        float sc[8][4];
        #pragma unroll
        for (int ni = 0; ni < 8; ni++) {
            sc[ni][0] = sc[ni][1] = sc[ni][2] = sc[ni][3] = 0.f;
            const uint32_t* kp = Kw + (ni * 8 + g) * 36 + t;
            #pragma unroll
            for (int kk = 0; kk < 4; kk++) {
                uint32_t bk[2] = { kp[kk * 8], kp[kk * 8 + 4] };
                mma16(sc[ni], aq[kk], bk);
            }
        }
        const int kb = kt * 64;
        #pragma unroll
        for (int ni = 0; ni < 8; ni++) {
            const int col = kb + ni * 8 + 2 * t;
            sc[ni][0] = (col     <= qrow0) ? sc[ni][0] * 0.125f : -1e30f;
            sc[ni][1] = (col + 1 <= qrow0) ? sc[ni][1] * 0.125f : -1e30f;
            sc[ni][2] = (col     <= qrow1) ? sc[ni][2] * 0.125f : -1e30f;
            sc[ni][3] = (col + 1 <= qrow1) ? sc[ni][3] * 0.125f : -1e30f;
        }
        float mt0 = -1e30f, mt1 = -1e30f;
        #pragma unroll
        for (int ni = 0; ni < 8; ni++) {
            mt0 = fmaxf(mt0, fmaxf(sc[ni][0], sc[ni][1]));
            mt1 = fmaxf(mt1, fmaxf(sc[ni][2], sc[ni][3]));
        }
        mt0 = fmaxf(mt0, __shfl_xor_sync(0xffffffffu, mt0, 1));
        mt0 = fmaxf(mt0, __shfl_xor_sync(0xffffffffu, mt0, 2));
        mt1 = fmaxf(mt1, __shfl_xor_sync(0xffffffffu, mt1, 1));
        mt1 = fmaxf(mt1, __shfl_xor_sync(0xffffffffu, mt1, 2));
        const float mn0 = fmaxf(m0, mt0), mn1 = fmaxf(m1, mt1);
        const float e0 = __expf(m0 - mn0), e1 = __expf(m1 - mn1);
        m0 = mn0; m1 = mn1;
        float ls0 = 0.f, ls1 = 0.f;
        #pragma unroll
        for (int ni = 0; ni < 8; ni++) {
            sc[ni][0] = __expf(sc[ni][0] - m0);
            sc[ni][1] = __expf(sc[ni][1] - m0);
            sc[ni][2] = __expf(sc[ni][2] - m1);
            sc[ni][3] = __expf(sc[ni][3] - m1);
            ls0 += sc[ni][0] + sc[ni][1];
            ls1 += sc[ni][2] + sc[ni][3];
        }
        l0 = l0 * e0 + ls0;
        l1 = l1 * e1 + ls1;
        #pragma unroll
        for (int ni = 0; ni < 8; ni++) {
            accO[ni][0] *= e0; accO[ni][1] *= e0;
            accO[ni][2] *= e1; accO[ni][3] *= e1;
        }
        // O += P @ V  (V row-major in smem; B frags via ldmatrix.x4.trans)
        #pragma unroll
        for (int j = 0; j < 4; j++) {
            uint32_t ap[4];
            ap[0] = packh2(sc[2*j][0],   sc[2*j][1]);
            ap[1] = packh2(sc[2*j][2],   sc[2*j][3]);
            ap[2] = packh2(sc[2*j+1][0], sc[2*j+1][1]);
            ap[3] = packh2(sc[2*j+1][2], sc[2*j+1][3]);
            #pragma unroll
            for (int nip = 0; nip < 4; nip++) {
                uint32_t br[4];
                const uint32_t addr = vbase +
                    4u * ((16 * j + (lane & 15)) * 36 + nip * 8 + 4 * (lane >> 4));
                ldsm4t(br, addr);
                mma16(accO[2 * nip],     ap, br + 0);
                mma16(accO[2 * nip + 1], ap, br + 2);
            }
        }
    }
    l0 += __shfl_xor_sync(0xffffffffu, l0, 1);
    l0 += __shfl_xor_sync(0xffffffffu, l0, 2);
    l1 += __shfl_xor_sync(0xffffffffu, l1, 1);
    l1 += __shfl_xor_sync(0xffffffffu, l1, 2);
    const float i0 = 1.f / l0, i1 = 1.f / l1;
    __half* op0 = Oh + (tokbase + qrow0) * HID + h * HD;
    __half* op1 = Oh + (tokbase + qrow1) * HID + h * HD;
    #pragma unroll
    for (int ni = 0; ni < 8; ni++) {
        const int col = ni * 8 + 2 * t;
        *(uint32_t*)(op0 + col) = packh2(accO[ni][0] * i0, accO[ni][1] * i0);
        *(uint32_t*)(op1 + col) = packh2(accO[ni][2] * i1, accO[ni][3] * i1);
    }
}

// ---------------- launch ----------------
extern "C" void kernel_launch(void* const* d_in, const int* in_sizes, int n_in,
                              void* d_out, int out_size)
{
    const float* hs     = (const float*)d_in[0];
    const float* wq     = (const float*)d_in[1];
    const float* wk     = (const float*)d_in[2];
    const float* wv     = (const float*)d_in[3];
    const float* wo     = (const float*)d_in[4];
    const float* w_gate = (const float*)d_in[5];
    const float* w_up   = (const float*)d_in[6];
    const float* w_down = (const float*)d_in[7];
    const float* norm1  = (const float*)d_in[8];
    const float* norm2  = (const float*)d_in[9];
    float* out = (float*)d_out;

    float* hid;
    __half *xnh, *qkvh, *attnh, *ynh, *gateh;
    __half *wqkvT, *woT, *wguT, *wdT;
    cudaGetSymbolAddress((void**)&hid,   g_hid);
    cudaGetSymbolAddress((void**)&xnh,   g_xnh);
    cudaGetSymbolAddress((void**)&qkvh,  g_qkvh);
    cudaGetSymbolAddress((void**)&attnh, g_attnh);
    cudaGetSymbolAddress((void**)&ynh,   g_ynh);
    cudaGetSymbolAddress((void**)&gateh, g_gateh);
    cudaGetSymbolAddress((void**)&wqkvT, g_wqkvT);
    cudaGetSymbolAddress((void**)&woT,   g_woT);
    cudaGetSymbolAddress((void**)&wguT,  g_wguT);
    cudaGetSymbolAddress((void**)&wdT,   g_wdT);

    cudaFuncSetAttribute(gemm_h<0>, cudaFuncAttributeMaxDynamicSharedMemorySize, GEMM_SMEM);
    cudaFuncSetAttribute(gemm_h<1>, cudaFuncAttributeMaxDynamicSharedMemorySize, GEMM_SMEM);
    cudaFuncSetAttribute(gemm_h<2>, cudaFuncAttributeMaxDynamicSharedMemorySize, GEMM_SMEM);

    const dim3 tb(32, 8);
    // weight conversion/transposition (fp32 [K][N] -> fp16 [N][K], with packing)
    transpose_h_kernel<<<dim3(2048/32, 2048/32), tb>>>(wq, wqkvT,                 2048, 2048, 1, 0);
    transpose_h_kernel<<<dim3( 512/32, 2048/32), tb>>>(wk, wqkvT + (size_t)KOFF*HID, 2048, 512, 1, 0);
    transpose_h_kernel<<<dim3( 512/32, 2048/32), tb>>>(wv, wqkvT + (size_t)VOFF*HID, 2048, 512, 1, 0);
    transpose_h_kernel<<<dim3(2048/32, 2048/32), tb>>>(wo, woT,                   2048, 2048, 1, 0);
    transpose_h_kernel<<<dim3(  FF/32, 2048/32), tb>>>(w_gate, wguT,              2048,   FF, 2, 0);
    transpose_h_kernel<<<dim3(  FF/32, 2048/32), tb>>>(w_up,   wguT,              2048,   FF, 2, 1);
    transpose_h_kernel<<<dim3(2048/32,   FF/32), tb>>>(w_down, wdT,                 FF, 2048, 1, 0);

    // 1) pre-norm -> fp16
    rmsnorm_h_kernel<<<TOK, 256>>>(hs, norm1, xnh);
    // 2) fused QKV projection + RoPE -> fp16 qkvh
    gemm_h<1><<<dim3(NQKV/BN, TOK/BM), 256, GEMM_SMEM>>>(TOK, NQKV, HID, xnh, wqkvT, nullptr, qkvh);
    // 3) causal GQA flash attention
    flash_attn_mma_kernel<<<dim3(SS/64, NH, BB), 128>>>(qkvh, attnh);
    // 4) output projection + residual -> fp32 hid
    gemm_h<0><<<dim3(2048/BN, TOK/BM), 256, GEMM_SMEM>>>(TOK, 2048, HID, attnh, woT, hs, hid);
    // 5) post-norm -> fp16
    rmsnorm_h_kernel<<<TOK, 256>>>(hid, norm2, ynh);
    // 6) fused gate/up projection + SwiGLU -> fp16 gateh
    gemm_h<2><<<dim3((2*FF)/BN, TOK/BM), 256, GEMM_SMEM>>>(TOK, 2*FF, HID, ynh, wguT, nullptr, gateh);
    // 7) down projection + residual -> fp32 output
    gemm_h<0><<<dim3(HID/BN, TOK/BM), 256, GEMM_SMEM>>>(TOK, HID, FF, gateh, wdT, hid, out);
}

// round 9
// speedup vs baseline: 9.4270x; 1.0246x over previous
#include <cuda_runtime.h>
#include <cuda_fp16.h>
#include <cstdint>

// Problem constants
#define HID   2048
#define NH    32
#define NKV   8
#define HD    64
#define FF    5632
#define BB    2
#define SS    2048
#define TOK   (BB*SS)           // 4096
#define NQKV  3072              // 2048 q + 512 k + 512 v
#define KOFF  2048
#define VOFF  2560

// ---------------- scratch (alloc-free: __device__ globals) ----------------
__device__ float  g_hid [TOK * HID];
__device__ __half g_xnh [TOK * HID];
__device__ __half g_qkvh[TOK * NQKV];
__device__ __half g_attnh[TOK * HID];
__device__ __half g_ynh [TOK * HID];
__device__ __half g_gateh[TOK * FF];
// transposed/interleaved (N-major, K-contiguous) fp16 weights
__device__ __half g_wqkvT[NQKV * HID];
__device__ __half g_woT  [HID * HID];
__device__ __half g_wguT [2 * FF * HID];     // row 2n = wg^T[n], row 2n+1 = wu^T[n]
__device__ __half g_wdT  [HID * FF];

// ---------------- helpers ----------------
__device__ __forceinline__ uint32_t s2u(const void* p) {
    uint32_t a;
    asm("{ .reg .u64 t; cvta.to.shared.u64 t, %1; cvt.u32.u64 %0, t; }" : "=r"(a) : "l"(p));
    return a;
}
__device__ __forceinline__ void cpa16(uint32_t s, const void* g) {
    asm volatile("cp.async.cg.shared.global [%0], [%1], 16;" :: "r"(s), "l"(g));
}
__device__ __forceinline__ void cp_commit() { asm volatile("cp.async.commit_group;" ::); }
template<int N> __device__ __forceinline__ void cp_wait() {
    asm volatile("cp.async.wait_group %0;" :: "n"(N));
}
__device__ __forceinline__ void mma16(float* c, const uint32_t* a, const uint32_t* b) {
    asm volatile(
        "mma.sync.aligned.m16n8k16.row.col.f32.f16.f16.f32 "
        "{%0,%1,%2,%3},{%4,%5,%6,%7},{%8,%9},{%0,%1,%2,%3};"
        : "+f"(c[0]), "+f"(c[1]), "+f"(c[2]), "+f"(c[3])
        : "r"(a[0]), "r"(a[1]), "r"(a[2]), "r"(a[3]), "r"(b[0]), "r"(b[1]));
}
__device__ __forceinline__ void ldsm4(uint32_t* r, uint32_t saddr) {
    asm volatile("ldmatrix.sync.aligned.m8n8.x4.shared.b16 {%0,%1,%2,%3}, [%4];"
        : "=r"(r[0]), "=r"(r[1]), "=r"(r[2]), "=r"(r[3]) : "r"(saddr));
}
__device__ __forceinline__ void ldsm4t(uint32_t* r, uint32_t saddr) {
    asm volatile("ldmatrix.sync.aligned.m8n8.x4.trans.shared.b16 {%0,%1,%2,%3}, [%4];"
        : "=r"(r[0]), "=r"(r[1]), "=r"(r[2]), "=r"(r[3]) : "r"(saddr));
}
__device__ __forceinline__ uint32_t packh2(float a, float b) {
    __half2 h = __floats2half2_rn(a, b);
    return *(uint32_t*)&h;
}

// ---------------- fp16 mma GEMM core, epilogue selected by MODE ----------------
// MODE 0: fp32 out (+optional RES).   MODE 1: QKV fused RoPE.   MODE 2: swiglu.
#define BM      128
#define BN      256
#define BKH     64
#define NSTAGE  3
#define HSTRW   36                         // row stride in 32-bit words (72 halves)
#define ATILEW  (BM * HSTRW)
#define BTILEW  (BN * HSTRW)
#define STAGEW  (ATILEW + BTILEW)
#define GEMM_SMEM (NSTAGE * STAGEW * 4)    // 165888 B

template<int MODE>
__global__ __launch_bounds__(256, 1) void gemm_h(
    int M, int N, int K,
    const __half* __restrict__ A, const __half* __restrict__ BT,
    const float* __restrict__ RES, void* __restrict__ Cout)
{
    extern __shared__ uint32_t smw[];
    const int tid = threadIdx.x;
    const int wid = tid >> 5, lane = tid & 31;
    const int g = lane >> 2, t = lane & 3;
    const int bm0 = blockIdx.y * BM, bn0 = blockIdx.x * BN;
    const int wm0 = (wid & 1) * 64;
    const int wn0 = (wid >> 1) * 64;

    // ldmatrix per-lane base offsets (byte): lanes grouped 8/quad
    const int laneq = lane >> 3, laner = lane & 7;
    const uint32_t aoffb = ((wm0 + (laneq & 1) * 8 + laner) * HSTRW + (laneq >> 1) * 4) * 4;
    const uint32_t boffb = ((wn0 + (laneq >> 1) * 8 + laner) * HSTRW + (laneq & 1) * 4) * 4;
    const uint32_t smbase = s2u(smw);

    float acc[4][8][4];
    #pragma unroll
    for (int mi = 0; mi < 4; mi++)
        #pragma unroll
        for (int ni = 0; ni < 8; ni++)
            #pragma unroll
            for (int u = 0; u < 4; u++) acc[mi][ni][u] = 0.f;

    const int NC = K / BKH;

    auto issue = [&](int j) {
        uint32_t* st = smw + (j % NSTAGE) * STAGEW;
        const int k0 = j * BKH;
        #pragma unroll
        for (int i = 0; i < 4; i++) {
            const int idx = tid + i * 256;
            const int r = idx >> 3, f = idx & 7;
            cpa16(s2u(st + r * HSTRW + f * 4), A + (size_t)(bm0 + r) * K + k0 + f * 8);
        }
        uint32_t* stb = st + ATILEW;
        #pragma unroll
        for (int i = 0; i < 8; i++) {
            const int idx = tid + i * 256;
            const int r = idx >> 3, f = idx & 7;
            cpa16(s2u(stb + r * HSTRW + f * 4), BT + (size_t)(bn0 + r) * K + k0 + f * 8);
        }
        cp_commit();
    };

    for (int j = 0; j < NSTAGE; j++) issue(j);

    for (int c = 0; c < NC; c++) {
        const int inflight_after = (c + NSTAGE <= NC ? c + NSTAGE : NC) - (c + 1);
        if (inflight_after >= 2)      cp_wait<2>();
        else if (inflight_after == 1) cp_wait<1>();
        else                          cp_wait<0>();
        __syncthreads();

        const uint32_t stb = smbase + (uint32_t)((c % NSTAGE) * (STAGEW * 4));
        const uint32_t ab = stb + aoffb;
        const uint32_t bb = stb + (uint32_t)(ATILEW * 4) + boffb;
        #pragma unroll
        for (int kk = 0; kk < 4; kk++) {
            const uint32_t kwb = kk * 32;           // 8 words = 32 bytes
            uint32_t af[4][4], bfp[4][4];
            #pragma unroll
            for (int mi = 0; mi < 4; mi++)
                ldsm4(af[mi], ab + mi * (16 * HSTRW * 4) + kwb);
            #pragma unroll
            for (int p = 0; p < 4; p++)
                ldsm4(bfp[p], bb + p * (16 * HSTRW * 4) + kwb);
            #pragma unroll
            for (int mi = 0; mi < 4; mi++)
                #pragma unroll
                for (int p = 0; p < 4; p++) {
                    mma16(acc[mi][2 * p],     af[mi], &bfp[p][0]);
                    mma16(acc[mi][2 * p + 1], af[mi], &bfp[p][2]);
                }
        }
        __syncthreads();
        if (c + NSTAGE < NC) issue(c + NSTAGE);
    }

    // ---------------- epilogues ----------------
    if (MODE == 0) {
        float* C = (float*)Cout;
        #pragma unroll
        for (int mi = 0; mi < 4; mi++) {
            const int row0 = bm0 + wm0 + mi * 16 + g;
            #pragma unroll
            for (int ni = 0; ni < 8; ni++) {
                const int col = bn0 + wn0 + ni * 8 + 2 * t;
                float2 d0 = make_float2(acc[mi][ni][0], acc[mi][ni][1]);
                float2 d1 = make_float2(acc[mi][ni][2], acc[mi][ni][3]);
                if (RES) {
                    float2 r0 = *(const float2*)(RES + (size_t)row0 * N + col);
                    float2 r1 = *(const float2*)(RES + (size_t)(row0 + 8) * N + col);
                    d0.x += r0.x; d0.y += r0.y;
                    d1.x += r1.x; d1.y += r1.y;
                }
                *(float2*)(C + (size_t)row0 * N + col)       = d0;
                *(float2*)(C + (size_t)(row0 + 8) * N + col) = d1;
            }
        }
    } else if (MODE == 1) {
        __half* O = (__half*)Cout;
        const int colbase = bn0 + wn0;           // 64-aligned => single head / segment
        if (colbase >= VOFF) {                   // V: plain fp16 convert
            #pragma unroll
            for (int mi = 0; mi < 4; mi++) {
                const int r0 = bm0 + wm0 + mi * 16 + g;
                __half* p0 = O + (size_t)r0 * NQKV;
                __half* p1 = O + (size_t)(r0 + 8) * NQKV;
                #pragma unroll
                for (int ni = 0; ni < 8; ni++) {
                    const int col = colbase + ni * 8 + 2 * t;
                    *(uint32_t*)(p0 + col) = packh2(acc[mi][ni][0], acc[mi][ni][1]);
                    *(uint32_t*)(p1 + col) = packh2(acc[mi][ni][2], acc[mi][ni][3]);
                }
            }
        } else {                                 // Q or K: fused RoPE
            float invf[4][2];
            #pragma unroll
            for (int ni = 0; ni < 4; ni++)
                #pragma unroll
                for (int u = 0; u < 2; u++) {
                    const int i = ni * 8 + 2 * t + u;
                    invf[ni][u] = powf(10000.0f, -(float)i / 32.0f);
                }
            #pragma unroll
            for (int mi = 0; mi < 4; mi++) {
                const int r0 = bm0 + wm0 + mi * 16 + g;
                const int r1 = r0 + 8;
                const float pos0 = (float)(r0 & (SS - 1));
                const float pos1 = (float)(r1 & (SS - 1));
                __half* p0 = O + (size_t)r0 * NQKV;
                __half* p1 = O + (size_t)r1 * NQKV;
                #pragma unroll
                for (int ni = 0; ni < 4; ni++) {
                    float lo0[2], hi0[2], lo1[2], hi1[2];
                    #pragma unroll
                    for (int u = 0; u < 2; u++) {
                        float s0, c0, s1, c1;
                        sincosf(pos0 * invf[ni][u], &s0, &c0);
                        sincosf(pos1 * invf[ni][u], &s1, &c1);
                        const float x1a = acc[mi][ni][u],     x2a = acc[mi][ni + 4][u];
                        const float x1b = acc[mi][ni][u + 2], x2b = acc[mi][ni + 4][u + 2];
                        lo0[u] = x1a * c0 - x2a * s0;  hi0[u] = x2a * c0 + x1a * s0;
                        lo1[u] = x1b * c1 - x2b * s1;  hi1[u] = x2b * c1 + x1b * s1;
                    }
                    const int col = colbase + ni * 8 + 2 * t;
                    *(uint32_t*)(p0 + col)      = packh2(lo0[0], lo0[1]);
                    *(uint32_t*)(p0 + col + 32) = packh2(hi0[0], hi0[1]);
                    *(uint32_t*)(p1 + col)      = packh2(lo1[0], lo1[1]);
                    *(uint32_t*)(p1 + col + 32) = packh2(hi1[0], hi1[1]);
                }
            }
        }
    } else {                                     // MODE 2: swiglu pairs (even=gate, odd=up)
        __half* O = (__half*)Cout;
        #pragma unroll
        for (int mi = 0; mi < 4; mi++) {
            const int r0 = bm0 + wm0 + mi * 16 + g;
            #pragma unroll
            for (int ni = 0; ni < 8; ni++) {
                const int c2 = (bn0 + wn0 + ni * 8) / 2 + t;
                const float ga = acc[mi][ni][0], ua = acc[mi][ni][1];
                const float gb = acc[mi][ni][2], ub = acc[mi][ni][3];
                O[(size_t)r0 * FF + c2]       = __float2half_rn(ga / (1.f + __expf(-ga)) * ua);
                O[(size_t)(r0 + 8) * FF + c2] = __float2half_rn(gb / (1.f + __expf(-gb)) * ub);
            }
        }
    }
}

// ---------------- ALL weight transposes in ONE kernel (half2 stores) ----------------
// Each 32x32 tile: read fp32 in[R][C], write fp16 out[(c*mul+add)][r].
__global__ __launch_bounds__(256) void transpose_all_kernel(
    const float* __restrict__ wq, const float* __restrict__ wk,
    const float* __restrict__ wv, const float* __restrict__ wo,
    const float* __restrict__ wg, const float* __restrict__ wu,
    const float* __restrict__ wd,
    __half* __restrict__ wqkvT, __half* __restrict__ woT,
    __half* __restrict__ wguT, __half* __restrict__ wdT)
{
    __shared__ float tbuf[32][33];
    const int bid = blockIdx.x;
    const float* in; __half* out;
    int R, C, mul, add, gx, local;
    if (bid < 4096)        { in = wq; out = wqkvT;                      R = 2048; C = 2048; mul = 1; add = 0; gx = 64;  local = bid; }
    else if (bid < 5120)   { in = wk; out = wqkvT + (size_t)KOFF * HID; R = 2048; C = 512;  mul = 1; add = 0; gx = 16;  local = bid - 4096; }
    else if (bid < 6144)   { in = wv; out = wqkvT + (size_t)VOFF * HID; R = 2048; C = 512;  mul = 1; add = 0; gx = 16;  local = bid - 5120; }
    else if (bid < 10240)  { in = wo; out = woT;                        R = 2048; C = 2048; mul = 1; add = 0; gx = 64;  local = bid - 6144; }
    else if (bid < 21504)  { in = wg; out = wguT;                       R = 2048; C = FF;   mul = 2; add = 0; gx = 176; local = bid - 10240; }
    else if (bid < 32768)  { in = wu; out = wguT;                       R = 2048; C = FF;   mul = 2; add = 1; gx = 176; local = bid - 21504; }
    else                   { in = wd; out = wdT;                        R = FF;   C = 2048; mul = 1; add = 0; gx = 64;  local = bid - 32768; }
    const int bx = (local % gx) * 32;
    const int by = (local / gx) * 32;
    const int tid = threadIdx.x;            // 256 threads (flat)
    const int x = tid & 31, y = tid >> 5;   // (32, 8)
    #pragma unroll
    for (int j = 0; j < 32; j += 8)
        tbuf[y + j][x] = in[(size_t)(by + y + j) * C + bx + x];
    __syncthreads();
    // stores: 512 items = 32 out-rows (b) x 16 col-pairs (ap); half2 => 128B/warp
    #pragma unroll
    for (int p = 0; p < 2; p++) {
        const int item = p * 256 + tid;
        const int b = item >> 4, ap = item & 15;
        const uint32_t v = packh2(tbuf[2 * ap][b], tbuf[2 * ap + 1][b]);
        *(uint32_t*)(out + ((size_t)(bx + b) * mul + add) * R + by + 2 * ap) = v;
    }
}

// ---------------- RMSNorm (fp16 output) ----------------
__global__ __launch_bounds__(256) void rmsnorm_h_kernel(
    const float* __restrict__ x, const float* __restrict__ w, __half* __restrict__ out)
{
    const int row = blockIdx.x;
    const float* xr = x + (size_t)row * HID;
    float ss = 0.f;
    for (int i = threadIdx.x; i < 512; i += 256) {
        float4 v = ((const float4*)xr)[i];
        ss += v.x*v.x + v.y*v.y + v.z*v.z + v.w*v.w;
    }
    #pragma unroll
    for (int o = 16; o > 0; o >>= 1) ss += __shfl_xor_sync(0xffffffffu, ss, o);
    __shared__ float red[8];
    if ((threadIdx.x & 31) == 0) red[threadIdx.x >> 5] = ss;
    __syncthreads();
    float tot = red[0];
    #pragma unroll
    for (int i = 1; i < 8; i++) tot += red[i];
    const float rs = rsqrtf(tot / (float)HID + 1e-6f);
    uint2* orow = (uint2*)(out + (size_t)row * HID);
    for (int i = threadIdx.x; i < 512; i += 256) {
        float4 v = ((const float4*)xr)[i];
        float4 ww = ((const float4*)w)[i];
        uint2 o;
        o.x = packh2(v.x * rs * ww.x, v.y * rs * ww.y);
        o.y = packh2(v.z * rs * ww.z, v.w * rs * ww.w);
        orow[i] = o;
    }
}

// ---------------- Flash attention, fp16 mma, qkv packed layout ----------------
__global__ __launch_bounds__(128) void flash_attn_mma_kernel(
    const __half* __restrict__ QKV, __half* __restrict__ Oh)
{
    __shared__ uint32_t Kw[64 * 36];   // [token][72 halves] row-major
    __shared__ uint32_t Vw[64 * 36];   // [token][72 halves] row-major (ldmatrix.trans for B)
    const int b = blockIdx.z, h = blockIdx.y, qt = blockIdx.x;
    const int kvh = h >> 2;
    const int tid = threadIdx.x;
    const int w = tid >> 5, lane = tid & 31;
    const int g = lane >> 2, t = lane & 3;
    const int q0 = qt * 64;
    const size_t tokbase = (size_t)b * SS;
    const uint32_t vbase = s2u(Vw);

    uint32_t aq[4][4];
    {
        const __half* qpg  = QKV + (tokbase + q0 + w * 16 + g)     * NQKV + h * HD;
        const __half* qpg8 = QKV + (tokbase + q0 + w * 16 + g + 8) * NQKV + h * HD;
        #pragma unroll
        for (int kk = 0; kk < 4; kk++) {
            aq[kk][0] = *(const uint32_t*)(qpg  + kk * 16 + 2 * t);
            aq[kk][1] = *(const uint32_t*)(qpg8 + kk * 16 + 2 * t);
            aq[kk][2] = *(const uint32_t*)(qpg  + kk * 16 + 8 + 2 * t);
            aq[kk][3] = *(const uint32_t*)(qpg8 + kk * 16 + 8 + 2 * t);
        }
    }

    float accO[8][4];
    #pragma unroll
    for (int ni = 0; ni < 8; ni++)
        #pragma unroll
        for (int u = 0; u < 4; u++) accO[ni][u] = 0.f;
    float m0 = -1e30f, m1 = -1e30f, l0 = 0.f, l1 = 0.f;
    const int qrow0 = q0 + w * 16 + g;
    const int qrow1 = qrow0 + 8;

    for (int kt = 0; kt <= qt; kt++) {
        __syncthreads();
        const __half* Kbase = QKV + (tokbase + kt * 64) * NQKV + KOFF + kvh * HD;
        const __half* Vbase = QKV + (tokbase + kt * 64) * NQKV + VOFF + kvh * HD;
        #pragma unroll
        for (int it = 0; it < 4; it++) {
            const int idx = tid + it * 128;          // 0..511
            const int row = idx >> 3, f = idx & 7;
            *(uint4*)&Kw[row * 36 + f * 4] = *(const uint4*)(Kbase + (size_t)row * NQKV + f * 8);
            *(uint4*)&Vw[row * 36 + f * 4] = *(const uint4*)(Vbase + (size_t)row * NQKV + f * 8);
        }
        __syncthreads();

        // S = Q @ K^T
        float sc[8][4];
        #pragma unroll
        for (int ni = 0; ni < 8; ni++) {
            sc[ni][0] = sc[ni][1] = sc[ni][2] = sc[ni][3] = 0.f;
            const uint32_t* kp = Kw + (ni * 8 + g) * 36 + t;
            #pragma unroll
            for (int kk = 0; kk < 4; kk++) {
                uint32_t bk[2] = { kp[kk * 8], kp[kk * 8 + 4] };
                mma16(sc[ni], aq[kk], bk);
            }
        }
        const int kb = kt * 64;
        #pragma unroll
        for (int ni = 0; ni < 8; ni++) {
            const int col = kb + ni * 8 + 2 * t;
            sc[ni][0] = (col     <= qrow0) ? sc[ni][0] * 0.125f : -1e30f;
            sc[ni][1] = (col + 1 <= qrow0) ? sc[ni][1] * 0.125f : -1e30f;
            sc[ni][2] = (col     <= qrow1) ? sc[ni][2] * 0.125f : -1e30f;
            sc[ni][3] = (col + 1 <= qrow1) ? sc[ni][3] * 0.125f : -1e30f;
        }
        float mt0 = -1e30f, mt1 = -1e30f;
        #pragma unroll
        for (int ni = 0; ni < 8; ni++) {
            mt0 = fmaxf(mt0, fmaxf(sc[ni][0], sc[ni][1]));
            mt1 = fmaxf(mt1, fmaxf(sc[ni][2], sc[ni][3]));
        }
        mt0 = fmaxf(mt0, __shfl_xor_sync(0xffffffffu, mt0, 1));
        mt0 = fmaxf(mt0, __shfl_xor_sync(0xffffffffu, mt0, 2));
        mt1 = fmaxf(mt1, __shfl_xor_sync(0xffffffffu, mt1, 1));
        mt1 = fmaxf(mt1, __shfl_xor_sync(0xffffffffu, mt1, 2));
        const float mn0 = fmaxf(m0, mt0), mn1 = fmaxf(m1, mt1);
        const float e0 = __expf(m0 - mn0), e1 = __expf(m1 - mn1);
        m0 = mn0; m1 = mn1;
        float ls0 = 0.f, ls1 = 0.f;
        #pragma unroll
        for (int ni = 0; ni < 8; ni++) {
            sc[ni][0] = __expf(sc[ni][0] - m0);
            sc[ni][1] = __expf(sc[ni][1] - m0);
            sc[ni][2] = __expf(sc[ni][2] - m1);
            sc[ni][3] = __expf(sc[ni][3] - m1);
            ls0 += sc[ni][0] + sc[ni][1];
            ls1 += sc[ni][2] + sc[ni][3];
        }
        l0 = l0 * e0 + ls0;
        l1 = l1 * e1 + ls1;
        #pragma unroll
        for (int ni = 0; ni < 8; ni++) {
            accO[ni][0] *= e0; accO[ni][1] *= e0;
            accO[ni][2] *= e1; accO[ni][3] *= e1;
        }
        // O += P @ V  (V row-major in smem; B frags via ldmatrix.x4.trans)
        #pragma unroll
        for (int j = 0; j < 4; j++) {
            uint32_t ap[4];
            ap[0] = packh2(sc[2*j][0],   sc[2*j][1]);
            ap[1] = packh2(sc[2*j][2],   sc[2*j][3]);
            ap[2] = packh2(sc[2*j+1][0], sc[2*j+1][1]);
            ap[3] = packh2(sc[2*j+1][2], sc[2*j+1][3]);
            #pragma unroll
            for (int nip = 0; nip < 4; nip++) {
                uint32_t br[4];
                const uint32_t addr = vbase +
                    4u * ((16 * j + (lane & 15)) * 36 + nip * 8 + 4 * (lane >> 4));
                ldsm4t(br, addr);
                mma16(accO[2 * nip],     ap, br + 0);
                mma16(accO[2 * nip + 1], ap, br + 2);
            }
        }
    }
    l0 += __shfl_xor_sync(0xffffffffu, l0, 1);
    l0 += __shfl_xor_sync(0xffffffffu, l0, 2);
    l1 += __shfl_xor_sync(0xffffffffu, l1, 1);
    l1 += __shfl_xor_sync(0xffffffffu, l1, 2);
    const float i0 = 1.f / l0, i1 = 1.f / l1;
    __half* op0 = Oh + (tokbase + qrow0) * HID + h * HD;
    __half* op1 = Oh + (tokbase + qrow1) * HID + h * HD;
    #pragma unroll
    for (int ni = 0; ni < 8; ni++) {
        const int col = ni * 8 + 2 * t;
        *(uint32_t*)(op0 + col) = packh2(accO[ni][0] * i0, accO[ni][1] * i0);
        *(uint32_t*)(op1 + col) = packh2(accO[ni][2] * i1, accO[ni][3] * i1);
    }
}

// ---------------- launch ----------------
extern "C" void kernel_launch(void* const* d_in, const int* in_sizes, int n_in,
                              void* d_out, int out_size)
{
    const float* hs     = (const float*)d_in[0];
    const float* wq     = (const float*)d_in[1];
    const float* wk     = (const float*)d_in[2];
    const float* wv     = (const float*)d_in[3];
    const float* wo     = (const float*)d_in[4];
    const float* w_gate = (const float*)d_in[5];
    const float* w_up   = (const float*)d_in[6];
    const float* w_down = (const float*)d_in[7];
    const float* norm1  = (const float*)d_in[8];
    const float* norm2  = (const float*)d_in[9];
    float* out = (float*)d_out;

    float* hid;
    __half *xnh, *qkvh, *attnh, *ynh, *gateh;
    __half *wqkvT, *woT, *wguT, *wdT;
    cudaGetSymbolAddress((void**)&hid,   g_hid);
    cudaGetSymbolAddress((void**)&xnh,   g_xnh);
    cudaGetSymbolAddress((void**)&qkvh,  g_qkvh);
    cudaGetSymbolAddress((void**)&attnh, g_attnh);
    cudaGetSymbolAddress((void**)&ynh,   g_ynh);
    cudaGetSymbolAddress((void**)&gateh, g_gateh);
    cudaGetSymbolAddress((void**)&wqkvT, g_wqkvT);
    cudaGetSymbolAddress((void**)&woT,   g_woT);
    cudaGetSymbolAddress((void**)&wguT,  g_wguT);
    cudaGetSymbolAddress((void**)&wdT,   g_wdT);

    cudaFuncSetAttribute(gemm_h<0>, cudaFuncAttributeMaxDynamicSharedMemorySize, GEMM_SMEM);
    cudaFuncSetAttribute(gemm_h<1>, cudaFuncAttributeMaxDynamicSharedMemorySize, GEMM_SMEM);
    cudaFuncSetAttribute(gemm_h<2>, cudaFuncAttributeMaxDynamicSharedMemorySize, GEMM_SMEM);

    // 0) all weight transposes in one launch (44032 tiles)
    transpose_all_kernel<<<44032, 256>>>(wq, wk, wv, wo, w_gate, w_up, w_down,
                                         wqkvT, woT, wguT, wdT);
    // 1) pre-norm -> fp16
    rmsnorm_h_kernel<<<TOK, 256>>>(hs, norm1, xnh);
    // 2) fused QKV projection + RoPE -> fp16 qkvh
    gemm_h<1><<<dim3(NQKV/BN, TOK/BM), 256, GEMM_SMEM>>>(TOK, NQKV, HID, xnh, wqkvT, nullptr, qkvh);
    // 3) causal GQA flash attention
    flash_attn_mma_kernel<<<dim3(SS/64, NH, BB), 128>>>(qkvh, attnh);
    // 4) output projection + residual -> fp32 hid
    gemm_h<0><<<dim3(2048/BN, TOK/BM), 256, GEMM_SMEM>>>(TOK, 2048, HID, attnh, woT, hs, hid);
    // 5) post-norm -> fp16
    rmsnorm_h_kernel<<<TOK, 256>>>(hid, norm2, ynh);
    // 6) fused gate/up projection + SwiGLU -> fp16 gateh
    gemm_h<2><<<dim3((2*FF)/BN, TOK/BM), 256, GEMM_SMEM>>>(TOK, 2*FF, HID, ynh, wguT, nullptr, gateh);
    // 7) down projection + residual -> fp32 output
    gemm_h<0><<<dim3(HID/BN, TOK/BM), 256, GEMM_SMEM>>>(TOK, HID, FF, gateh, wdT, hid, out);
}

// round 12
// speedup vs baseline: 9.6994x; 1.0289x over previous
#include <cuda_runtime.h>
#include <cuda_fp16.h>
#include <cstdint>

// Problem constants
#define HID   2048
#define NH    32
#define NKV   8
#define HD    64
#define FF    5632
#define BB    2
#define SS    2048
#define TOK   (BB*SS)           // 4096
#define NQKV  3072              // 2048 q + 512 k + 512 v
#define KOFF  2048
#define VOFF  2560

// ---------------- scratch (alloc-free: __device__ globals) ----------------
__device__ float  g_hid [TOK * HID];
__device__ __half g_xnh [TOK * HID];
__device__ __half g_qkvh[TOK * NQKV];
__device__ __half g_attnh[TOK * HID];
__device__ __half g_ynh [TOK * HID];
__device__ __half g_gateh[TOK * FF];
// transposed/interleaved (N-major, K-contiguous) fp16 weights
__device__ __half g_wqkvT[NQKV * HID];
__device__ __half g_woT  [HID * HID];
__device__ __half g_wguT [2 * FF * HID];     // row 2n = wg^T[n], row 2n+1 = wu^T[n]
__device__ __half g_wdT  [HID * FF];

// ---------------- helpers ----------------
__device__ __forceinline__ uint32_t s2u(const void* p) {
    uint32_t a;
    asm("{ .reg .u64 t; cvta.to.shared.u64 t, %1; cvt.u32.u64 %0, t; }" : "=r"(a) : "l"(p));
    return a;
}
__device__ __forceinline__ void cpa16(uint32_t s, const void* g) {
    asm volatile("cp.async.cg.shared.global [%0], [%1], 16;" :: "r"(s), "l"(g));
}
__device__ __forceinline__ void cp_commit() { asm volatile("cp.async.commit_group;" ::); }
template<int N> __device__ __forceinline__ void cp_wait() {
    asm volatile("cp.async.wait_group %0;" :: "n"(N));
}
__device__ __forceinline__ void mma16(float* c, const uint32_t* a, const uint32_t* b) {
    asm volatile(
        "mma.sync.aligned.m16n8k16.row.col.f32.f16.f16.f32 "
        "{%0,%1,%2,%3},{%4,%5,%6,%7},{%8,%9},{%0,%1,%2,%3};"
        : "+f"(c[0]), "+f"(c[1]), "+f"(c[2]), "+f"(c[3])
        : "r"(a[0]), "r"(a[1]), "r"(a[2]), "r"(a[3]), "r"(b[0]), "r"(b[1]));
}
__device__ __forceinline__ void ldsm4(uint32_t* r, uint32_t saddr) {
    asm volatile("ldmatrix.sync.aligned.m8n8.x4.shared.b16 {%0,%1,%2,%3}, [%4];"
        : "=r"(r[0]), "=r"(r[1]), "=r"(r[2]), "=r"(r[3]) : "r"(saddr));
}
__device__ __forceinline__ void ldsm4t(uint32_t* r, uint32_t saddr) {
    asm volatile("ldmatrix.sync.aligned.m8n8.x4.trans.shared.b16 {%0,%1,%2,%3}, [%4];"
        : "=r"(r[0]), "=r"(r[1]), "=r"(r[2]), "=r"(r[3]) : "r"(saddr));
}
__device__ __forceinline__ uint32_t packh2(float a, float b) {
    __half2 h = __floats2half2_rn(a, b);
    return *(uint32_t*)&h;
}

// ---------------- fp16 mma GEMM core, epilogue selected by MODE ----------------
// MODE 0: fp32 out (+optional RES).   MODE 1: QKV fused RoPE.   MODE 2: swiglu.
#define BM      128
#define BN      256
#define BKH     64
#define NSTAGE  3
#define HSTRW   36                         // row stride in 32-bit words (72 halves)
#define ATILEW  (BM * HSTRW)
#define BTILEW  (BN * HSTRW)
#define STAGEW  (ATILEW + BTILEW)
#define GEMM_SMEM (NSTAGE * STAGEW * 4)    // 165888 B

template<int MODE>
__global__ __launch_bounds__(256, 1) void gemm_h(
    int M, int N, int K,
    const __half* __restrict__ A, const __half* __restrict__ BT,
    const float* __restrict__ RES, void* __restrict__ Cout)
{
    extern __shared__ uint32_t smw[];
    const int tid = threadIdx.x;
    const int wid = tid >> 5, lane = tid & 31;
    const int g = lane >> 2, t = lane & 3;
    const int bm0 = blockIdx.y * BM, bn0 = blockIdx.x * BN;
    const int wm0 = (wid & 1) * 64;
    const int wn0 = (wid >> 1) * 64;

    const int laneq = lane >> 3, laner = lane & 7;
    const uint32_t aoffb = ((wm0 + (laneq & 1) * 8 + laner) * HSTRW + (laneq >> 1) * 4) * 4;
    const uint32_t boffb = ((wn0 + (laneq >> 1) * 8 + laner) * HSTRW + (laneq & 1) * 4) * 4;
    const uint32_t smbase = s2u(smw);

    float acc[4][8][4];
    #pragma unroll
    for (int mi = 0; mi < 4; mi++)
        #pragma unroll
        for (int ni = 0; ni < 8; ni++)
            #pragma unroll
            for (int u = 0; u < 4; u++) acc[mi][ni][u] = 0.f;

    const int NC = K / BKH;

    auto issue = [&](int j) {
        uint32_t* st = smw + (j % NSTAGE) * STAGEW;
        const int k0 = j * BKH;
        #pragma unroll
        for (int i = 0; i < 4; i++) {
            const int idx = tid + i * 256;
            const int r = idx >> 3, f = idx & 7;
            cpa16(s2u(st + r * HSTRW + f * 4), A + (size_t)(bm0 + r) * K + k0 + f * 8);
        }
        uint32_t* stb = st + ATILEW;
        #pragma unroll
        for (int i = 0; i < 8; i++) {
            const int idx = tid + i * 256;
            const int r = idx >> 3, f = idx & 7;
            cpa16(s2u(stb + r * HSTRW + f * 4), BT + (size_t)(bn0 + r) * K + k0 + f * 8);
        }
        cp_commit();
    };

    for (int j = 0; j < NSTAGE; j++) issue(j);

    for (int c = 0; c < NC; c++) {
        const int inflight_after = (c + NSTAGE <= NC ? c + NSTAGE : NC) - (c + 1);
        if (inflight_after >= 2)      cp_wait<2>();
        else if (inflight_after == 1) cp_wait<1>();
        else                          cp_wait<0>();
        __syncthreads();

        const uint32_t stb = smbase + (uint32_t)((c % NSTAGE) * (STAGEW * 4));
        const uint32_t ab = stb + aoffb;
        const uint32_t bb = stb + (uint32_t)(ATILEW * 4) + boffb;
        #pragma unroll
        for (int kk = 0; kk < 4; kk++) {
            const uint32_t kwb = kk * 32;           // 8 words = 32 bytes
            uint32_t af[4][4], bfp[4][4];
            #pragma unroll
            for (int mi = 0; mi < 4; mi++)
                ldsm4(af[mi], ab + mi * (16 * HSTRW * 4) + kwb);
            #pragma unroll
            for (int p = 0; p < 4; p++)
                ldsm4(bfp[p], bb + p * (16 * HSTRW * 4) + kwb);
            #pragma unroll
            for (int mi = 0; mi < 4; mi++)
                #pragma unroll
                for (int p = 0; p < 4; p++) {
                    mma16(acc[mi][2 * p],     af[mi], &bfp[p][0]);
                    mma16(acc[mi][2 * p + 1], af[mi], &bfp[p][2]);
                }
        }
        __syncthreads();
        if (c + NSTAGE < NC) issue(c + NSTAGE);
    }

    // ---------------- epilogues ----------------
    if (MODE == 0) {
        float* C = (float*)Cout;
        #pragma unroll
        for (int mi = 0; mi < 4; mi++) {
            const int row0 = bm0 + wm0 + mi * 16 + g;
            #pragma unroll
            for (int ni = 0; ni < 8; ni++) {
                const int col = bn0 + wn0 + ni * 8 + 2 * t;
                float2 d0 = make_float2(acc[mi][ni][0], acc[mi][ni][1]);
                float2 d1 = make_float2(acc[mi][ni][2], acc[mi][ni][3]);
                if (RES) {
                    float2 r0 = *(const float2*)(RES + (size_t)row0 * N + col);
                    float2 r1 = *(const float2*)(RES + (size_t)(row0 + 8) * N + col);
                    d0.x += r0.x; d0.y += r0.y;
                    d1.x += r1.x; d1.y += r1.y;
                }
                *(float2*)(C + (size_t)row0 * N + col)       = d0;
                *(float2*)(C + (size_t)(row0 + 8) * N + col) = d1;
            }
        }
    } else if (MODE == 1) {
        __half* O = (__half*)Cout;
        const int colbase = bn0 + wn0;           // 64-aligned => single head / segment
        if (colbase >= VOFF) {                   // V: plain fp16 convert
            #pragma unroll
            for (int mi = 0; mi < 4; mi++) {
                const int r0 = bm0 + wm0 + mi * 16 + g;
                __half* p0 = O + (size_t)r0 * NQKV;
                __half* p1 = O + (size_t)(r0 + 8) * NQKV;
                #pragma unroll
                for (int ni = 0; ni < 8; ni++) {
                    const int col = colbase + ni * 8 + 2 * t;
                    *(uint32_t*)(p0 + col) = packh2(acc[mi][ni][0], acc[mi][ni][1]);
                    *(uint32_t*)(p1 + col) = packh2(acc[mi][ni][2], acc[mi][ni][3]);
                }
            }
        } else {                                 // Q or K: fused RoPE
            float invf[4][2];
            #pragma unroll
            for (int ni = 0; ni < 4; ni++)
                #pragma unroll
                for (int u = 0; u < 2; u++) {
                    const int i = ni * 8 + 2 * t + u;
                    invf[ni][u] = powf(10000.0f, -(float)i / 32.0f);
                }
            #pragma unroll
            for (int mi = 0; mi < 4; mi++) {
                const int r0 = bm0 + wm0 + mi * 16 + g;
                const int r1 = r0 + 8;
                const float pos0 = (float)(r0 & (SS - 1));
                const float pos1 = (float)(r1 & (SS - 1));
                __half* p0 = O + (size_t)r0 * NQKV;
                __half* p1 = O + (size_t)r1 * NQKV;
                #pragma unroll
                for (int ni = 0; ni < 4; ni++) {
                    float lo0[2], hi0[2], lo1[2], hi1[2];
                    #pragma unroll
                    for (int u = 0; u < 2; u++) {
                        float s0, c0, s1, c1;
                        sincosf(pos0 * invf[ni][u], &s0, &c0);
                        sincosf(pos1 * invf[ni][u], &s1, &c1);
                        const float x1a = acc[mi][ni][u],     x2a = acc[mi][ni + 4][u];
                        const float x1b = acc[mi][ni][u + 2], x2b = acc[mi][ni + 4][u + 2];
                        lo0[u] = x1a * c0 - x2a * s0;  hi0[u] = x2a * c0 + x1a * s0;
                        lo1[u] = x1b * c1 - x2b * s1;  hi1[u] = x2b * c1 + x1b * s1;
                    }
                    const int col = colbase + ni * 8 + 2 * t;
                    *(uint32_t*)(p0 + col)      = packh2(lo0[0], lo0[1]);
                    *(uint32_t*)(p0 + col + 32) = packh2(hi0[0], hi0[1]);
                    *(uint32_t*)(p1 + col)      = packh2(lo1[0], lo1[1]);
                    *(uint32_t*)(p1 + col + 32) = packh2(hi1[0], hi1[1]);
                }
            }
        }
    } else {                                     // MODE 2: swiglu pairs (even=gate, odd=up)
        __half* O = (__half*)Cout;
        #pragma unroll
        for (int mi = 0; mi < 4; mi++) {
            const int r0 = bm0 + wm0 + mi * 16 + g;
            #pragma unroll
            for (int ni = 0; ni < 8; ni++) {
                const int c2 = (bn0 + wn0 + ni * 8) / 2 + t;
                const float ga = acc[mi][ni][0], ua = acc[mi][ni][1];
                const float gb = acc[mi][ni][2], ub = acc[mi][ni][3];
                O[(size_t)r0 * FF + c2]       = __float2half_rn(ga / (1.f + __expf(-ga)) * ua);
                O[(size_t)(r0 + 8) * FF + c2] = __float2half_rn(gb / (1.f + __expf(-gb)) * ub);
            }
        }
    }
}

// ---------------- ALL weight transposes, 64x64 tiles (128B warp stores) ----------------
__global__ __launch_bounds__(256) void transpose_all_kernel(
    const float* __restrict__ wq, const float* __restrict__ wk,
    const float* __restrict__ wv, const float* __restrict__ wo,
    const float* __restrict__ wg, const float* __restrict__ wu,
    const float* __restrict__ wd,
    __half* __restrict__ wqkvT, __half* __restrict__ woT,
    __half* __restrict__ wguT, __half* __restrict__ wdT)
{
    __shared__ float tbuf[64][65];
    const int bid = blockIdx.x;
    const float* in; __half* out;
    int R, C, mul, add, gx, local;
    if (bid < 1024)        { in = wq; out = wqkvT;                      R = 2048; C = 2048; mul = 1; add = 0; gx = 32; local = bid; }
    else if (bid < 1280)   { in = wk; out = wqkvT + (size_t)KOFF * HID; R = 2048; C = 512;  mul = 1; add = 0; gx = 8;  local = bid - 1024; }
    else if (bid < 1536)   { in = wv; out = wqkvT + (size_t)VOFF * HID; R = 2048; C = 512;  mul = 1; add = 0; gx = 8;  local = bid - 1280; }
    else if (bid < 2560)   { in = wo; out = woT;                        R = 2048; C = 2048; mul = 1; add = 0; gx = 32; local = bid - 1536; }
    else if (bid < 5376)   { in = wg; out = wguT;                       R = 2048; C = FF;   mul = 2; add = 0; gx = 88; local = bid - 2560; }
    else if (bid < 8192)   { in = wu; out = wguT;                       R = 2048; C = FF;   mul = 2; add = 1; gx = 88; local = bid - 5376; }
    else                   { in = wd; out = wdT;                        R = FF;   C = 2048; mul = 1; add = 0; gx = 32; local = bid - 8192; }
    const int bx = (local % gx) * 64;
    const int by = (local / gx) * 64;
    const int tid = threadIdx.x;
    const int x = tid & 63, y = tid >> 6;       // (64, 4)
    #pragma unroll
    for (int j = 0; j < 64; j += 4)
        tbuf[y + j][x] = in[(size_t)(by + y + j) * C + bx + x];
    __syncthreads();
    const int w8 = tid >> 5, lane = tid & 31;   // 8 warps, 8 out-rows each; 128B per row
    #pragma unroll
    for (int j = 0; j < 8; j++) {
        const int orow = w8 * 8 + j;
        const uint32_t v = packh2(tbuf[2 * lane][orow], tbuf[2 * lane + 1][orow]);
        *(uint32_t*)(out + ((size_t)(bx + orow) * mul + add) * R + by + 2 * lane) = v;
    }
}

// ---------------- RMSNorm (fp16 output) ----------------
__global__ __launch_bounds__(256) void rmsnorm_h_kernel(
    const float* __restrict__ x, const float* __restrict__ w, __half* __restrict__ out)
{
    const int row = blockIdx.x;
    const float* xr = x + (size_t)row * HID;
    float ss = 0.f;
    for (int i = threadIdx.x; i < 512; i += 256) {
        float4 v = ((const float4*)xr)[i];
        ss += v.x*v.x + v.y*v.y + v.z*v.z + v.w*v.w;
    }
    #pragma unroll
    for (int o = 16; o > 0; o >>= 1) ss += __shfl_xor_sync(0xffffffffu, ss, o);
    __shared__ float red[8];
    if ((threadIdx.x & 31) == 0) red[threadIdx.x >> 5] = ss;
    __syncthreads();
    float tot = red[0];
    #pragma unroll
    for (int i = 1; i < 8; i++) tot += red[i];
    const float rs = rsqrtf(tot / (float)HID + 1e-6f);
    uint2* orow = (uint2*)(out + (size_t)row * HID);
    for (int i = threadIdx.x; i < 512; i += 256) {
        float4 v = ((const float4*)xr)[i];
        float4 ww = ((const float4*)w)[i];
        uint2 o;
        o.x = packh2(v.x * rs * ww.x, v.y * rs * ww.y);
        o.y = packh2(v.z * rs * ww.z, v.w * rs * ww.w);
        orow[i] = o;
    }
}

// ---------------- Flash attention: cp.async double-buffer + ldmatrix K ----------------
// grid (S/64, NH, B), qt reversed (heaviest blocks first); 128 threads (4 warps).
#define AT_BUFW 4608    // words per buffer: K 64x36 + V 64x36
#define AT_VOFW 2304

__global__ __launch_bounds__(128) void flash_attn_mma_kernel(
    const __half* __restrict__ QKV, __half* __restrict__ Oh)
{
    __shared__ uint32_t KVs[2 * AT_BUFW];      // 36.9 KB, double-buffered
    const int b = blockIdx.z, h = blockIdx.y;
    const int qt = gridDim.x - 1 - blockIdx.x; // reversed: big qt first
    const int kvh = h >> 2;
    const int tid = threadIdx.x;
    const int w = tid >> 5, lane = tid & 31;
    const int g = lane >> 2, t = lane & 3;
    const int laneq = lane >> 3, laner = lane & 7;
    const int q0 = qt * 64;
    const size_t tokbase = (size_t)b * SS;
    const uint32_t smbase = s2u(KVs);
    // ldmatrix lane offset for K B-frags (same pattern as gemm boffb)
    const uint32_t koff = (uint32_t)((((laneq >> 1) * 8 + laner) * 36) * 4 + (laneq & 1) * 16);

    uint32_t aq[4][4];
    {
        const __half* qpg  = QKV + (tokbase + q0 + w * 16 + g)     * NQKV + h * HD;
        const __half* qpg8 = QKV + (tokbase + q0 + w * 16 + g + 8) * NQKV + h * HD;
        #pragma unroll
        for (int kk = 0; kk < 4; kk++) {
            aq[kk][0] = *(const uint32_t*)(qpg  + kk * 16 + 2 * t);
            aq[kk][1] = *(const uint32_t*)(qpg8 + kk * 16 + 2 * t);
            aq[kk][2] = *(const uint32_t*)(qpg  + kk * 16 + 8 + 2 * t);
            aq[kk][3] = *(const uint32_t*)(qpg8 + kk * 16 + 8 + 2 * t);
        }
    }

    auto load_tile = [&](int kt, int buf) {
        const __half* Kb = QKV + (tokbase + kt * 64) * NQKV + KOFF + kvh * HD;
        const __half* Vb = QKV + (tokbase + kt * 64) * NQKV + VOFF + kvh * HD;
        const uint32_t kd = smbase + (uint32_t)(buf * (AT_BUFW * 4));
        #pragma unroll
        for (int it = 0; it < 4; it++) {
            const int idx = tid + it * 128;
            const int row = idx >> 3, f = idx & 7;
            const uint32_t so = (uint32_t)((row * 36 + f * 4) * 4);
            cpa16(kd + so,                 Kb + (size_t)row * NQKV + f * 8);
            cpa16(kd + AT_VOFW * 4 + so,   Vb + (size_t)row * NQKV + f * 8);
        }
        cp_commit();
    };

    float accO[8][4];
    #pragma unroll
    for (int ni = 0; ni < 8; ni++)
        #pragma unroll
        for (int u = 0; u < 4; u++) accO[ni][u] = 0.f;
    float m0 = -1e30f, m1 = -1e30f, l0 = 0.f, l1 = 0.f;
    const int qrow0 = q0 + w * 16 + g;
    const int qrow1 = qrow0 + 8;

    load_tile(0, 0);

    for (int kt = 0; kt <= qt; kt++) {
        __syncthreads();                         // prev compute done -> safe to refill other buf
        if (kt + 1 <= qt) { load_tile(kt + 1, (kt + 1) & 1); cp_wait<1>(); }
        else              { cp_wait<0>(); }
        __syncthreads();                         // tile kt visible to all warps

        const uint32_t kb32 = smbase + (uint32_t)((kt & 1) * (AT_BUFW * 4));
        const uint32_t vb32 = kb32 + AT_VOFW * 4;

        // S = Q @ K^T (K B-frags via ldmatrix.x4)
        float sc[8][4];
        #pragma unroll
        for (int ni = 0; ni < 8; ni++)
            sc[ni][0] = sc[ni][1] = sc[ni][2] = sc[ni][3] = 0.f;
        #pragma unroll
        for (int p = 0; p < 4; p++) {
            #pragma unroll
            for (int kk = 0; kk < 4; kk++) {
                uint32_t br[4];
                ldsm4(br, kb32 + p * (16 * 36 * 4) + kk * 32 + koff);
                mma16(sc[2 * p],     aq[kk], &br[0]);
                mma16(sc[2 * p + 1], aq[kk], &br[2]);
            }
        }
        const int kb = kt * 64;
        #pragma unroll
        for (int ni = 0; ni < 8; ni++) {
            const int col = kb + ni * 8 + 2 * t;
            sc[ni][0] = (col     <= qrow0) ? sc[ni][0] * 0.125f : -1e30f;
            sc[ni][1] = (col + 1 <= qrow0) ? sc[ni][1] * 0.125f : -1e30f;
            sc[ni][2] = (col     <= qrow1) ? sc[ni][2] * 0.125f : -1e30f;
            sc[ni][3] = (col + 1 <= qrow1) ? sc[ni][3] * 0.125f : -1e30f;
        }
        float mt0 = -1e30f, mt1 = -1e30f;
        #pragma unroll
        for (int ni = 0; ni < 8; ni++) {
            mt0 = fmaxf(mt0, fmaxf(sc[ni][0], sc[ni][1]));
            mt1 = fmaxf(mt1, fmaxf(sc[ni][2], sc[ni][3]));
        }
        mt0 = fmaxf(mt0, __shfl_xor_sync(0xffffffffu, mt0, 1));
        mt0 = fmaxf(mt0, __shfl_xor_sync(0xffffffffu, mt0, 2));
        mt1 = fmaxf(mt1, __shfl_xor_sync(0xffffffffu, mt1, 1));
        mt1 = fmaxf(mt1, __shfl_xor_sync(0xffffffffu, mt1, 2));
        const float mn0 = fmaxf(m0, mt0), mn1 = fmaxf(m1, mt1);
        const float e0 = __expf(m0 - mn0), e1 = __expf(m1 - mn1);
        m0 = mn0; m1 = mn1;
        float ls0 = 0.f, ls1 = 0.f;
        #pragma unroll
        for (int ni = 0; ni < 8; ni++) {
            sc[ni][0] = __expf(sc[ni][0] - m0);
            sc[ni][1] = __expf(sc[ni][1] - m0);
            sc[ni][2] = __expf(sc[ni][2] - m1);
            sc[ni][3] = __expf(sc[ni][3] - m1);
            ls0 += sc[ni][0] + sc[ni][1];
            ls1 += sc[ni][2] + sc[ni][3];
        }
        l0 = l0 * e0 + ls0;
        l1 = l1 * e1 + ls1;
        #pragma unroll
        for (int ni = 0; ni < 8; ni++) {
            accO[ni][0] *= e0; accO[ni][1] *= e0;
            accO[ni][2] *= e1; accO[ni][3] *= e1;
        }
        // O += P @ V  (V row-major; B frags via ldmatrix.x4.trans)
        #pragma unroll
        for (int j = 0; j < 4; j++) {
            uint32_t ap[4];
            ap[0] = packh2(sc[2*j][0],   sc[2*j][1]);
            ap[1] = packh2(sc[2*j][2],   sc[2*j][3]);
            ap[2] = packh2(sc[2*j+1][0], sc[2*j+1][1]);
            ap[3] = packh2(sc[2*j+1][2], sc[2*j+1][3]);
            #pragma unroll
            for (int nip = 0; nip < 4; nip++) {
                uint32_t br[4];
                const uint32_t addr = vb32 +
                    4u * ((16 * j + (lane & 15)) * 36 + nip * 8 + 4 * (lane >> 4));
                ldsm4t(br, addr);
                mma16(accO[2 * nip],     ap, br + 0);
                mma16(accO[2 * nip + 1], ap, br + 2);
            }
        }
    }
    l0 += __shfl_xor_sync(0xffffffffu, l0, 1);
    l0 += __shfl_xor_sync(0xffffffffu, l0, 2);
    l1 += __shfl_xor_sync(0xffffffffu, l1, 1);
    l1 += __shfl_xor_sync(0xffffffffu, l1, 2);
    const float i0 = 1.f / l0, i1 = 1.f / l1;
    __half* op0 = Oh + (tokbase + qrow0) * HID + h * HD;
    __half* op1 = Oh + (tokbase + qrow1) * HID + h * HD;
    #pragma unroll
    for (int ni = 0; ni < 8; ni++) {
        const int col = ni * 8 + 2 * t;
        *(uint32_t*)(op0 + col) = packh2(accO[ni][0] * i0, accO[ni][1] * i0);
        *(uint32_t*)(op1 + col) = packh2(accO[ni][2] * i1, accO[ni][3] * i1);
    }
}

// ---------------- launch ----------------
extern "C" void kernel_launch(void* const* d_in, const int* in_sizes, int n_in,
                              void* d_out, int out_size)
{
    const float* hs     = (const float*)d_in[0];
    const float* wq     = (const float*)d_in[1];
    const float* wk     = (const float*)d_in[2];
    const float* wv     = (const float*)d_in[3];
    const float* wo     = (const float*)d_in[4];
    const float* w_gate = (const float*)d_in[5];
    const float* w_up   = (const float*)d_in[6];
    const float* w_down = (const float*)d_in[7];
    const float* norm1  = (const float*)d_in[8];
    const float* norm2  = (const float*)d_in[9];
    float* out = (float*)d_out;

    float* hid;
    __half *xnh, *qkvh, *attnh, *ynh, *gateh;
    __half *wqkvT, *woT, *wguT, *wdT;
    cudaGetSymbolAddress((void**)&hid,   g_hid);
    cudaGetSymbolAddress((void**)&xnh,   g_xnh);
    cudaGetSymbolAddress((void**)&qkvh,  g_qkvh);
    cudaGetSymbolAddress((void**)&attnh, g_attnh);
    cudaGetSymbolAddress((void**)&ynh,   g_ynh);
    cudaGetSymbolAddress((void**)&gateh, g_gateh);
    cudaGetSymbolAddress((void**)&wqkvT, g_wqkvT);
    cudaGetSymbolAddress((void**)&woT,   g_woT);
    cudaGetSymbolAddress((void**)&wguT,  g_wguT);
    cudaGetSymbolAddress((void**)&wdT,   g_wdT);

    cudaFuncSetAttribute(gemm_h<0>, cudaFuncAttributeMaxDynamicSharedMemorySize, GEMM_SMEM);
    cudaFuncSetAttribute(gemm_h<1>, cudaFuncAttributeMaxDynamicSharedMemorySize, GEMM_SMEM);
    cudaFuncSetAttribute(gemm_h<2>, cudaFuncAttributeMaxDynamicSharedMemorySize, GEMM_SMEM);

    // 0) all weight transposes in one launch (11008 x 64x64 tiles)
    transpose_all_kernel<<<11008, 256>>>(wq, wk, wv, wo, w_gate, w_up, w_down,
                                         wqkvT, woT, wguT, wdT);
    // 1) pre-norm -> fp16
    rmsnorm_h_kernel<<<TOK, 256>>>(hs, norm1, xnh);
    // 2) fused QKV projection + RoPE -> fp16 qkvh
    gemm_h<1><<<dim3(NQKV/BN, TOK/BM), 256, GEMM_SMEM>>>(TOK, NQKV, HID, xnh, wqkvT, nullptr, qkvh);
    // 3) causal GQA flash attention
    flash_attn_mma_kernel<<<dim3(SS/64, NH, BB), 128>>>(qkvh, attnh);
    // 4) output projection + residual -> fp32 hid
    gemm_h<0><<<dim3(2048/BN, TOK/BM), 256, GEMM_SMEM>>>(TOK, 2048, HID, attnh, woT, hs, hid);
    // 5) post-norm -> fp16
    rmsnorm_h_kernel<<<TOK, 256>>>(hid, norm2, ynh);
    // 6) fused gate/up projection + SwiGLU -> fp16 gateh
    gemm_h<2><<<dim3((2*FF)/BN, TOK/BM), 256, GEMM_SMEM>>>(TOK, 2*FF, HID, ynh, wguT, nullptr, gateh);
    // 7) down projection + residual -> fp32 output
    gemm_h<0><<<dim3(HID/BN, TOK/BM), 256, GEMM_SMEM>>>(TOK, HID, FF, gateh, wdT, hid, out);
}